// round 1
// baseline (speedup 1.0000x reference)
#include <cuda_runtime.h>

#define NN 50000
#define EE 800000

// ---------------- scratch (static device globals; no allocation) ----------------
__device__ float g_buf0[NN * 256];
__device__ float g_buf1[NN * 256];
__device__ float g_dis[NN];
__device__ int   g_deg[NN];
__device__ int   g_off[NN + 1];
__device__ int   g_cur[NN];
__device__ int   g_csrc[EE];
__device__ float g_cw[EE];

// ---------------- graph preprocessing ----------------
__global__ void zero_deg_kernel() {
    int i = blockIdx.x * blockDim.x + threadIdx.x;
    if (i < NN) g_deg[i] = 0;
}

__global__ void count_deg_kernel(const int* __restrict__ dst) {
    int e = blockIdx.x * blockDim.x + threadIdx.x;
    if (e < EE) atomicAdd(&g_deg[dst[e]], 1);
}

// Single-block exclusive scan over deg -> offsets; also dis = rsqrt(deg+1), cursor init.
__global__ void scan_kernel() {
    __shared__ int s[1024];
    const int t = threadIdx.x;
    const int CH = (NN + 1023) / 1024;  // 49
    int start = t * CH;
    int end = min(start + CH, NN);
    int sum = 0;
    for (int i = start; i < end; i++) sum += g_deg[i];
    s[t] = sum;
    __syncthreads();
    for (int off = 1; off < 1024; off <<= 1) {
        int v = (t >= off) ? s[t - off] : 0;
        __syncthreads();
        s[t] += v;
        __syncthreads();
    }
    int run = (t == 0) ? 0 : s[t - 1];
    for (int i = start; i < end; i++) {
        g_off[i] = run;
        g_cur[i] = run;
        g_dis[i] = rsqrtf((float)(g_deg[i] + 1));
        run += g_deg[i];
    }
    if (start < NN && end == NN) g_off[NN] = run;
}

__global__ void fill_csr_kernel(const int* __restrict__ src, const int* __restrict__ dst) {
    int e = blockIdx.x * blockDim.x + threadIdx.x;
    if (e < EE) {
        int s = src[e];
        int d = dst[e];
        int pos = atomicAdd(&g_cur[d], 1);
        g_csrc[pos] = s;
        g_cw[pos] = g_dis[s] * g_dis[d];
    }
}

// ---------------- SGEMM: C[M,N] = A[M,K] @ B[K,N] (+ optional bias & leaky relu) ----------------
#define TBM 64
#define TBN 64
#define TBK 16

template <bool BIAS_ACT>
__global__ __launch_bounds__(256) void sgemm_kernel(
    const float* __restrict__ A, const float* __restrict__ B,
    const float* __restrict__ bias, float* __restrict__ C,
    int M, int N, int K) {
    __shared__ float As[TBK][TBM];  // transposed A tile
    __shared__ float Bs[TBK][TBN];

    const int tid = threadIdx.x;
    const int bm = blockIdx.y * TBM;
    const int bn = blockIdx.x * TBN;
    const int tx = tid % 16;
    const int ty = tid / 16;

    // load mappings
    const int aRow = tid / 4;          // 0..63
    const int aCol4 = (tid % 4) * 4;   // 0,4,8,12
    const int bRow = tid / 16;         // 0..15
    const int bCol4 = (tid % 16) * 4;  // 0..60

    float acc[4][4] = {};

    for (int k0 = 0; k0 < K; k0 += TBK) {
        float4 av;
        int gr = bm + aRow;
        if (gr < M)
            av = *(const float4*)(A + (size_t)gr * K + k0 + aCol4);
        else
            av = make_float4(0.f, 0.f, 0.f, 0.f);
        As[aCol4 + 0][aRow] = av.x;
        As[aCol4 + 1][aRow] = av.y;
        As[aCol4 + 2][aRow] = av.z;
        As[aCol4 + 3][aRow] = av.w;

        float4 bv = *(const float4*)(B + (size_t)(k0 + bRow) * N + bn + bCol4);
        *(float4*)(&Bs[bRow][bCol4]) = bv;
        __syncthreads();

#pragma unroll
        for (int k = 0; k < TBK; k++) {
            float4 a4 = *(const float4*)(&As[k][ty * 4]);
            float4 b4 = *(const float4*)(&Bs[k][tx * 4]);
            float ar[4] = {a4.x, a4.y, a4.z, a4.w};
            float br[4] = {b4.x, b4.y, b4.z, b4.w};
#pragma unroll
            for (int i = 0; i < 4; i++)
#pragma unroll
                for (int j = 0; j < 4; j++) acc[i][j] += ar[i] * br[j];
        }
        __syncthreads();
    }

#pragma unroll
    for (int i = 0; i < 4; i++) {
        int r = bm + ty * 4 + i;
        if (r < M) {
            float4 o;
            float v0 = acc[i][0], v1 = acc[i][1], v2 = acc[i][2], v3 = acc[i][3];
            if (BIAS_ACT) {
                int c = bn + tx * 4;
                v0 += bias[c + 0];
                v1 += bias[c + 1];
                v2 += bias[c + 2];
                v3 += bias[c + 3];
                v0 = v0 > 0.f ? v0 : 0.01f * v0;
                v1 = v1 > 0.f ? v1 : 0.01f * v1;
                v2 = v2 > 0.f ? v2 : 0.01f * v2;
                v3 = v3 > 0.f ? v3 : 0.01f * v3;
            }
            o.x = v0; o.y = v1; o.z = v2; o.w = v3;
            *(float4*)(C + (size_t)r * N + bn + tx * 4) = o;
        }
    }
}

// ---------------- gather aggregation: H = lrelu(Dis^-1/2 (A+I) Dis^-1/2 Y + b) ----------------
// one warp per node; CSR-by-dst gather (no float atomics).
template <int C>
__global__ __launch_bounds__(256) void agg_kernel(
    const float* __restrict__ Y, const float* __restrict__ bias, float* __restrict__ H) {
    int node = (blockIdx.x * blockDim.x + threadIdx.x) >> 5;
    int lane = threadIdx.x & 31;
    if (node >= NN) return;

    float dn = g_dis[node];
    float selfw = dn * dn;
    int beg = g_off[node];
    int end = g_off[node + 1];

    if constexpr (C == 64) {
        const float2* yr = (const float2*)(Y + (size_t)node * 64);
        float2 v = yr[lane];
        float ax = selfw * v.x, ay = selfw * v.y;
        int i = beg;
        for (; i + 2 <= end; i += 2) {
            int s0 = g_csrc[i], s1 = g_csrc[i + 1];
            float w0 = g_cw[i], w1 = g_cw[i + 1];
            float2 u0 = ((const float2*)(Y + (size_t)s0 * 64))[lane];
            float2 u1 = ((const float2*)(Y + (size_t)s1 * 64))[lane];
            ax += w0 * u0.x + w1 * u1.x;
            ay += w0 * u0.y + w1 * u1.y;
        }
        if (i < end) {
            int s0 = g_csrc[i];
            float w0 = g_cw[i];
            float2 u0 = ((const float2*)(Y + (size_t)s0 * 64))[lane];
            ax += w0 * u0.x;
            ay += w0 * u0.y;
        }
        float2 b = ((const float2*)bias)[lane];
        ax += b.x; ay += b.y;
        ax = ax > 0.f ? ax : 0.01f * ax;
        ay = ay > 0.f ? ay : 0.01f * ay;
        float2 o; o.x = ax; o.y = ay;
        ((float2*)(H + (size_t)node * 64))[lane] = o;
    } else {
        constexpr int V = C / 128;  // float4 chunks per lane (1 or 2)
        float4 acc[V];
        const float4* yr = (const float4*)(Y + (size_t)node * C);
#pragma unroll
        for (int v = 0; v < V; v++) {
            float4 u = yr[lane + 32 * v];
            acc[v].x = selfw * u.x; acc[v].y = selfw * u.y;
            acc[v].z = selfw * u.z; acc[v].w = selfw * u.w;
        }
        int i = beg;
        for (; i + 2 <= end; i += 2) {
            int s0 = g_csrc[i], s1 = g_csrc[i + 1];
            float w0 = g_cw[i], w1 = g_cw[i + 1];
            const float4* r0 = (const float4*)(Y + (size_t)s0 * C);
            const float4* r1 = (const float4*)(Y + (size_t)s1 * C);
#pragma unroll
            for (int v = 0; v < V; v++) {
                float4 u0 = r0[lane + 32 * v];
                float4 u1 = r1[lane + 32 * v];
                acc[v].x += w0 * u0.x + w1 * u1.x;
                acc[v].y += w0 * u0.y + w1 * u1.y;
                acc[v].z += w0 * u0.z + w1 * u1.z;
                acc[v].w += w0 * u0.w + w1 * u1.w;
            }
        }
        if (i < end) {
            int s0 = g_csrc[i];
            float w0 = g_cw[i];
            const float4* r0 = (const float4*)(Y + (size_t)s0 * C);
#pragma unroll
            for (int v = 0; v < V; v++) {
                float4 u0 = r0[lane + 32 * v];
                acc[v].x += w0 * u0.x;
                acc[v].y += w0 * u0.y;
                acc[v].z += w0 * u0.z;
                acc[v].w += w0 * u0.w;
            }
        }
#pragma unroll
        for (int v = 0; v < V; v++) {
            float4 b = ((const float4*)bias)[lane + 32 * v];
            float4 o;
            o.x = acc[v].x + b.x; o.y = acc[v].y + b.y;
            o.z = acc[v].z + b.z; o.w = acc[v].w + b.w;
            o.x = o.x > 0.f ? o.x : 0.01f * o.x;
            o.y = o.y > 0.f ? o.y : 0.01f * o.y;
            o.z = o.z > 0.f ? o.z : 0.01f * o.z;
            o.w = o.w > 0.f ? o.w : 0.01f * o.w;
            ((float4*)(H + (size_t)node * C))[lane + 32 * v] = o;
        }
    }
}

// ---------------- final projection: out = h3[N,64] @ W_out[64,1] + b_out ----------------
__global__ __launch_bounds__(256) void out_kernel(
    const float* __restrict__ H, const float* __restrict__ Wout,
    const float* __restrict__ bout, float* __restrict__ out) {
    int node = (blockIdx.x * blockDim.x + threadIdx.x) >> 5;
    int lane = threadIdx.x & 31;
    if (node >= NN) return;
    const float* h = H + (size_t)node * 64;
    float v = h[lane] * Wout[lane] + h[lane + 32] * Wout[lane + 32];
#pragma unroll
    for (int o = 16; o > 0; o >>= 1) v += __shfl_down_sync(0xffffffffu, v, o);
    if (lane == 0) out[node] = v + bout[0];
}

// ---------------- launch ----------------
extern "C" void kernel_launch(void* const* d_in, const int* in_sizes, int n_in,
                              void* d_out, int out_size) {
    const float* x    = (const float*)d_in[0];
    const int*   ei   = (const int*)d_in[1];
    const float* W_in = (const float*)d_in[2];
    const float* b_in = (const float*)d_in[3];
    const float* W1   = (const float*)d_in[4];
    const float* b1   = (const float*)d_in[5];
    const float* W2   = (const float*)d_in[6];
    const float* b2   = (const float*)d_in[7];
    const float* W3   = (const float*)d_in[8];
    const float* b3   = (const float*)d_in[9];
    const float* Wo   = (const float*)d_in[10];
    const float* bo   = (const float*)d_in[11];
    float* out = (float*)d_out;

    const int* src = ei;
    const int* dst = ei + EE;

    float *buf0, *buf1;
    cudaGetSymbolAddress((void**)&buf0, g_buf0);
    cudaGetSymbolAddress((void**)&buf1, g_buf1);

    // graph preprocessing (deg / dis / CSR-by-dst) — shared by all 3 conv layers
    zero_deg_kernel<<<(NN + 255) / 256, 256>>>();
    count_deg_kernel<<<(EE + 255) / 256, 256>>>(dst);
    scan_kernel<<<1, 1024>>>();
    fill_csr_kernel<<<(EE + 255) / 256, 256>>>(src, dst);

    dim3 blk(256);
    // h0 = lrelu(x @ W_in + b_in)   [N,128]
    sgemm_kernel<true><<<dim3(128 / TBN, (NN + TBM - 1) / TBM), blk>>>(x, W_in, b_in, buf0, NN, 128, 128);
    // layer 1: Y = h0 @ W1 [N,256]; h1 = lrelu(agg(Y) + b1)
    sgemm_kernel<false><<<dim3(256 / TBN, (NN + TBM - 1) / TBM), blk>>>(buf0, W1, nullptr, buf1, NN, 256, 128);
    agg_kernel<256><<<(NN + 7) / 8, 256>>>(buf1, b1, buf0);
    // layer 2: Y = h1 @ W2 [N,128]
    sgemm_kernel<false><<<dim3(128 / TBN, (NN + TBM - 1) / TBM), blk>>>(buf0, W2, nullptr, buf1, NN, 128, 256);
    agg_kernel<128><<<(NN + 7) / 8, 256>>>(buf1, b2, buf0);
    // layer 3: Y = h2 @ W3 [N,64]
    sgemm_kernel<false><<<dim3(64 / TBN, (NN + TBM - 1) / TBM), blk>>>(buf0, W3, nullptr, buf1, NN, 64, 128);
    agg_kernel<64><<<(NN + 7) / 8, 256>>>(buf1, b3, buf0);
    // out = h3 @ W_out + b_out
    out_kernel<<<(NN + 7) / 8, 256>>>(buf0, Wo, bo, out);
}

// round 2
// speedup vs baseline: 1.3896x; 1.3896x over previous
#include <cuda_runtime.h>
#include <cstdint>

#define NN 50000
#define EE 800000

// ---------------- scratch (static device globals; no allocation) ----------------
__device__ float g_buf0[NN * 256];
__device__ float g_buf1[NN * 256];
__device__ float g_dis[NN];
__device__ int   g_deg[NN];
__device__ int   g_off[NN + 1];
__device__ int   g_cur[NN];
__device__ int   g_csrc[EE];
__device__ float g_cw[EE];

// ---------------- graph preprocessing ----------------
__global__ void zero_deg_kernel() {
    int i = blockIdx.x * blockDim.x + threadIdx.x;
    if (i < NN) g_deg[i] = 0;
}

__global__ void count_deg_kernel(const int* __restrict__ dst) {
    int e = blockIdx.x * blockDim.x + threadIdx.x;
    if (e < EE) atomicAdd(&g_deg[dst[e]], 1);
}

// Single-block exclusive scan over deg -> offsets; also dis = rsqrt(deg+1), cursor init.
__global__ void scan_kernel() {
    __shared__ int s[1024];
    const int t = threadIdx.x;
    const int CH = (NN + 1023) / 1024;  // 49
    int start = t * CH;
    int end = min(start + CH, NN);
    int sum = 0;
    for (int i = start; i < end; i++) sum += g_deg[i];
    s[t] = sum;
    __syncthreads();
    for (int off = 1; off < 1024; off <<= 1) {
        int v = (t >= off) ? s[t - off] : 0;
        __syncthreads();
        s[t] += v;
        __syncthreads();
    }
    int run = (t == 0) ? 0 : s[t - 1];
    for (int i = start; i < end; i++) {
        g_off[i] = run;
        g_cur[i] = run;
        g_dis[i] = rsqrtf((float)(g_deg[i] + 1));
        run += g_deg[i];
    }
    if (start < NN && end == NN) g_off[NN] = run;
}

__global__ void fill_csr_kernel(const int* __restrict__ src, const int* __restrict__ dst) {
    int e = blockIdx.x * blockDim.x + threadIdx.x;
    if (e < EE) {
        int s = src[e];
        int d = dst[e];
        int pos = atomicAdd(&g_cur[d], 1);
        g_csrc[pos] = s;
        g_cw[pos] = g_dis[s] * g_dis[d];
    }
}

// ---------------- TF32 tensor-core GEMM ----------------
// C[M,N] = A[M,K] @ B[K,N] (+ optional bias & leaky relu)
// Block tile: 128 x NT. 8 warps (4 m x 2 n). Warp tile: 32 x NT/2.
// mma.sync.aligned.m16n8k8.row.col.f32.tf32.tf32.f32

__device__ __forceinline__ uint32_t f2tf32(float x) {
    uint32_t r;
    asm("cvt.rna.tf32.f32 %0, %1;" : "=r"(r) : "f"(x));
    return r;
}

#define MMA_TF32(d, a, b)                                                             \
    asm volatile(                                                                     \
        "mma.sync.aligned.m16n8k8.row.col.f32.tf32.tf32.f32 "                         \
        "{%0,%1,%2,%3}, {%4,%5,%6,%7}, {%8,%9}, {%0,%1,%2,%3};"                       \
        : "+f"((d)[0]), "+f"((d)[1]), "+f"((d)[2]), "+f"((d)[3])                      \
        : "r"((a)[0]), "r"((a)[1]), "r"((a)[2]), "r"((a)[3]), "r"((b)[0]), "r"((b)[1]))

template <int NT, bool BIAS_ACT>
__global__ __launch_bounds__(256) void gemm_tc_kernel(
    const float* __restrict__ A, const float* __restrict__ B,
    const float* __restrict__ bias, float* __restrict__ C,
    int M, int N, int K) {
    constexpr int NF = NT / 16;        // n-frags per warp (warp n-tile = NT/2, frag n = 8)
    constexpr int BS = NT + 4;         // padded B smem row stride
    __shared__ uint32_t As[128 * 20];  // [m][k] stride 20 (16 + 4 pad)
    __shared__ uint32_t Bs[16 * BS];   // [k][n] stride BS

    const int tid = threadIdx.x;
    const int lane = tid & 31;
    const int wid = tid >> 5;
    const int wm = (wid & 3) * 32;       // warp m offset within block
    const int wn = (wid >> 2) * (NT / 2);  // warp n offset within block
    const int g = lane >> 2;             // group id 0..7
    const int t4 = lane & 3;             // 0..3
    const int bm = blockIdx.y * 128;
    const int bn = blockIdx.x * NT;

    float c[2][NF][4] = {};

    // global->smem load mappings
    const int aR = tid >> 2;            // 0..63? no: 256/4 = 64... need 128 rows x 16 cols
    // A chunk 128x16 floats = 2048; 256 threads * 8 floats (2 float4)
    // thread handles rows tid>>1? Use: float4 id = it*256+tid over 512; row=id/4, col4=(id%4)*4
    (void)aR;

    for (int k0 = 0; k0 < K; k0 += 16) {
        // ---- load A chunk: 128 rows x 16 cols ----
#pragma unroll
        for (int it = 0; it < 2; it++) {
            int id = it * 256 + tid;       // 0..511 float4 ids
            int r = id >> 2;               // 0..127
            int cc = (id & 3) * 4;         // 0,4,8,12
            float4 v;
            if (bm + r < M)
                v = *(const float4*)(A + (size_t)(bm + r) * K + k0 + cc);
            else
                v = make_float4(0.f, 0.f, 0.f, 0.f);
            uint32_t* p = &As[r * 20 + cc];
            p[0] = f2tf32(v.x);
            p[1] = f2tf32(v.y);
            p[2] = f2tf32(v.z);
            p[3] = f2tf32(v.w);
        }
        // ---- load B chunk: 16 rows x NT cols ----
#pragma unroll
        for (int it = 0; it < NT / 64; it++) {
            int id = it * 256 + tid;        // float4 ids over 16*NT/4
            int r = id / (NT / 4);          // k row 0..15
            int cc = (id % (NT / 4)) * 4;   // col
            float4 v = *(const float4*)(B + (size_t)(k0 + r) * N + bn + cc);
            uint32_t* p = &Bs[r * BS + cc];
            p[0] = f2tf32(v.x);
            p[1] = f2tf32(v.y);
            p[2] = f2tf32(v.z);
            p[3] = f2tf32(v.w);
        }
        __syncthreads();

#pragma unroll
        for (int s = 0; s < 2; s++) {
            uint32_t a[2][4];
#pragma unroll
            for (int mf = 0; mf < 2; mf++) {
                int r0 = (wm + mf * 16 + g) * 20 + s * 8 + t4;
                int r1 = (wm + mf * 16 + g + 8) * 20 + s * 8 + t4;
                a[mf][0] = As[r0];
                a[mf][1] = As[r1];
                a[mf][2] = As[r0 + 4];
                a[mf][3] = As[r1 + 4];
            }
            uint32_t b[NF][2];
#pragma unroll
            for (int nf = 0; nf < NF; nf++) {
                int col = wn + nf * 8 + g;
                b[nf][0] = Bs[(s * 8 + t4) * BS + col];
                b[nf][1] = Bs[(s * 8 + t4 + 4) * BS + col];
            }
#pragma unroll
            for (int mf = 0; mf < 2; mf++)
#pragma unroll
                for (int nf = 0; nf < NF; nf++) MMA_TF32(c[mf][nf], a[mf], b[nf]);
        }
        __syncthreads();
    }

    // ---- epilogue ----
#pragma unroll
    for (int mf = 0; mf < 2; mf++) {
        int r0 = bm + wm + mf * 16 + g;
        int r1 = r0 + 8;
#pragma unroll
        for (int nf = 0; nf < NF; nf++) {
            int col = bn + wn + nf * 8 + 2 * t4;
            float v0 = c[mf][nf][0], v1 = c[mf][nf][1];
            float v2 = c[mf][nf][2], v3 = c[mf][nf][3];
            if (BIAS_ACT) {
                float bb0 = bias[col], bb1 = bias[col + 1];
                v0 += bb0; v1 += bb1; v2 += bb0; v3 += bb1;
                v0 = v0 > 0.f ? v0 : 0.01f * v0;
                v1 = v1 > 0.f ? v1 : 0.01f * v1;
                v2 = v2 > 0.f ? v2 : 0.01f * v2;
                v3 = v3 > 0.f ? v3 : 0.01f * v3;
            }
            if (r0 < M) { float2 o; o.x = v0; o.y = v1; *(float2*)(C + (size_t)r0 * N + col) = o; }
            if (r1 < M) { float2 o; o.x = v2; o.y = v3; *(float2*)(C + (size_t)r1 * N + col) = o; }
        }
    }
}

// ---------------- gather aggregation: H = lrelu(Dis^-1/2 (A+I) Dis^-1/2 Y + b) ----------------
template <int C>
__global__ __launch_bounds__(256) void agg_kernel(
    const float* __restrict__ Y, const float* __restrict__ bias, float* __restrict__ H) {
    int node = (blockIdx.x * blockDim.x + threadIdx.x) >> 5;
    int lane = threadIdx.x & 31;
    if (node >= NN) return;

    float dn = g_dis[node];
    float selfw = dn * dn;
    int beg = g_off[node];
    int end = g_off[node + 1];

    if constexpr (C == 64) {
        const float2* yr = (const float2*)(Y + (size_t)node * 64);
        float2 v = yr[lane];
        float ax = selfw * v.x, ay = selfw * v.y;
        int i = beg;
        for (; i + 2 <= end; i += 2) {
            int s0 = g_csrc[i], s1 = g_csrc[i + 1];
            float w0 = g_cw[i], w1 = g_cw[i + 1];
            float2 u0 = ((const float2*)(Y + (size_t)s0 * 64))[lane];
            float2 u1 = ((const float2*)(Y + (size_t)s1 * 64))[lane];
            ax += w0 * u0.x + w1 * u1.x;
            ay += w0 * u0.y + w1 * u1.y;
        }
        if (i < end) {
            int s0 = g_csrc[i];
            float w0 = g_cw[i];
            float2 u0 = ((const float2*)(Y + (size_t)s0 * 64))[lane];
            ax += w0 * u0.x;
            ay += w0 * u0.y;
        }
        float2 b = ((const float2*)bias)[lane];
        ax += b.x; ay += b.y;
        ax = ax > 0.f ? ax : 0.01f * ax;
        ay = ay > 0.f ? ay : 0.01f * ay;
        float2 o; o.x = ax; o.y = ay;
        ((float2*)(H + (size_t)node * 64))[lane] = o;
    } else {
        constexpr int V = C / 128;
        float4 acc[V];
        const float4* yr = (const float4*)(Y + (size_t)node * C);
#pragma unroll
        for (int v = 0; v < V; v++) {
            float4 u = yr[lane + 32 * v];
            acc[v].x = selfw * u.x; acc[v].y = selfw * u.y;
            acc[v].z = selfw * u.z; acc[v].w = selfw * u.w;
        }
        int i = beg;
        for (; i + 2 <= end; i += 2) {
            int s0 = g_csrc[i], s1 = g_csrc[i + 1];
            float w0 = g_cw[i], w1 = g_cw[i + 1];
            const float4* r0 = (const float4*)(Y + (size_t)s0 * C);
            const float4* r1 = (const float4*)(Y + (size_t)s1 * C);
#pragma unroll
            for (int v = 0; v < V; v++) {
                float4 u0 = r0[lane + 32 * v];
                float4 u1 = r1[lane + 32 * v];
                acc[v].x += w0 * u0.x + w1 * u1.x;
                acc[v].y += w0 * u0.y + w1 * u1.y;
                acc[v].z += w0 * u0.z + w1 * u1.z;
                acc[v].w += w0 * u0.w + w1 * u1.w;
            }
        }
        if (i < end) {
            int s0 = g_csrc[i];
            float w0 = g_cw[i];
            const float4* r0 = (const float4*)(Y + (size_t)s0 * C);
#pragma unroll
            for (int v = 0; v < V; v++) {
                float4 u0 = r0[lane + 32 * v];
                acc[v].x += w0 * u0.x;
                acc[v].y += w0 * u0.y;
                acc[v].z += w0 * u0.z;
                acc[v].w += w0 * u0.w;
            }
        }
#pragma unroll
        for (int v = 0; v < V; v++) {
            float4 b = ((const float4*)bias)[lane + 32 * v];
            float4 o;
            o.x = acc[v].x + b.x; o.y = acc[v].y + b.y;
            o.z = acc[v].z + b.z; o.w = acc[v].w + b.w;
            o.x = o.x > 0.f ? o.x : 0.01f * o.x;
            o.y = o.y > 0.f ? o.y : 0.01f * o.y;
            o.z = o.z > 0.f ? o.z : 0.01f * o.z;
            o.w = o.w > 0.f ? o.w : 0.01f * o.w;
            ((float4*)(H + (size_t)node * C))[lane + 32 * v] = o;
        }
    }
}

// ---------------- final projection: out = h3[N,64] @ W_out[64,1] + b_out ----------------
__global__ __launch_bounds__(256) void out_kernel(
    const float* __restrict__ H, const float* __restrict__ Wout,
    const float* __restrict__ bout, float* __restrict__ out) {
    int node = (blockIdx.x * blockDim.x + threadIdx.x) >> 5;
    int lane = threadIdx.x & 31;
    if (node >= NN) return;
    const float* h = H + (size_t)node * 64;
    float v = h[lane] * Wout[lane] + h[lane + 32] * Wout[lane + 32];
#pragma unroll
    for (int o = 16; o > 0; o >>= 1) v += __shfl_down_sync(0xffffffffu, v, o);
    if (lane == 0) out[node] = v + bout[0];
}

// ---------------- launch ----------------
extern "C" void kernel_launch(void* const* d_in, const int* in_sizes, int n_in,
                              void* d_out, int out_size) {
    const float* x    = (const float*)d_in[0];
    const int*   ei   = (const int*)d_in[1];
    const float* W_in = (const float*)d_in[2];
    const float* b_in = (const float*)d_in[3];
    const float* W1   = (const float*)d_in[4];
    const float* b1   = (const float*)d_in[5];
    const float* W2   = (const float*)d_in[6];
    const float* b2   = (const float*)d_in[7];
    const float* W3   = (const float*)d_in[8];
    const float* b3   = (const float*)d_in[9];
    const float* Wo   = (const float*)d_in[10];
    const float* bo   = (const float*)d_in[11];
    float* out = (float*)d_out;

    const int* src = ei;
    const int* dst = ei + EE;

    float *buf0, *buf1;
    cudaGetSymbolAddress((void**)&buf0, g_buf0);
    cudaGetSymbolAddress((void**)&buf1, g_buf1);

    // graph preprocessing (deg / dis / CSR-by-dst) — shared by all 3 conv layers
    zero_deg_kernel<<<(NN + 255) / 256, 256>>>();
    count_deg_kernel<<<(EE + 255) / 256, 256>>>(dst);
    scan_kernel<<<1, 1024>>>();
    fill_csr_kernel<<<(EE + 255) / 256, 256>>>(src, dst);

    const int MT = (NN + 127) / 128;  // 391 m-tiles
    // h0 = lrelu(x @ W_in + b_in)   [N,128]
    gemm_tc_kernel<128, true><<<dim3(1, MT), 256>>>(x, W_in, b_in, buf0, NN, 128, 128);
    // layer 1: Y = h0 @ W1 [N,256]; h1 = lrelu(agg(Y) + b1)
    gemm_tc_kernel<128, false><<<dim3(2, MT), 256>>>(buf0, W1, nullptr, buf1, NN, 256, 128);
    agg_kernel<256><<<(NN + 7) / 8, 256>>>(buf1, b1, buf0);
    // layer 2: Y = h1 @ W2 [N,128]
    gemm_tc_kernel<128, false><<<dim3(1, MT), 256>>>(buf0, W2, nullptr, buf1, NN, 128, 256);
    agg_kernel<128><<<(NN + 7) / 8, 256>>>(buf1, b2, buf0);
    // layer 3: Y = h2 @ W3 [N,64]
    gemm_tc_kernel<64, false><<<dim3(1, MT), 256>>>(buf0, W3, nullptr, buf1, NN, 64, 128);
    agg_kernel<64><<<(NN + 7) / 8, 256>>>(buf1, b3, buf0);
    // out = h3 @ W_out + b_out
    out_kernel<<<(NN + 7) / 8, 256>>>(buf0, Wo, bo, out);
}

// round 3
// speedup vs baseline: 1.5188x; 1.0930x over previous
#include <cuda_runtime.h>
#include <cstdint>

#define NN 50000
#define EE 800000

// ---------------- scratch (static device globals; no allocation) ----------------
__device__ float g_buf0[NN * 256];
__device__ float g_buf1[NN * 256];
__device__ float g_dis[NN];
__device__ int   g_deg[NN];
__device__ int   g_off[NN + 1];
__device__ int   g_cur[NN];
__device__ int   g_csrc[EE];
__device__ float g_cw[EE];

// ---------------- graph preprocessing ----------------
__global__ void zero_deg_kernel() {
    int i = blockIdx.x * blockDim.x + threadIdx.x;
    if (i < NN) g_deg[i] = 0;
}

__global__ void count_deg_kernel(const int* __restrict__ dst) {
    int e = blockIdx.x * blockDim.x + threadIdx.x;
    if (e < EE) atomicAdd(&g_deg[dst[e]], 1);
}

// Single-block exclusive scan over deg -> offsets; also dis = rsqrt(deg+1), cursor init.
__global__ void scan_kernel() {
    __shared__ int s[1024];
    const int t = threadIdx.x;
    const int CH = (NN + 1023) / 1024;  // 49
    int start = t * CH;
    int end = min(start + CH, NN);
    int sum = 0;
    for (int i = start; i < end; i++) sum += g_deg[i];
    s[t] = sum;
    __syncthreads();
    for (int off = 1; off < 1024; off <<= 1) {
        int v = (t >= off) ? s[t - off] : 0;
        __syncthreads();
        s[t] += v;
        __syncthreads();
    }
    int run = (t == 0) ? 0 : s[t - 1];
    for (int i = start; i < end; i++) {
        g_off[i] = run;
        g_cur[i] = run;
        g_dis[i] = rsqrtf((float)(g_deg[i] + 1));
        run += g_deg[i];
    }
    if (start < NN && end == NN) g_off[NN] = run;
}

__global__ void fill_csr_kernel(const int* __restrict__ src, const int* __restrict__ dst) {
    int e = blockIdx.x * blockDim.x + threadIdx.x;
    if (e < EE) {
        int s = src[e];
        int d = dst[e];
        int pos = atomicAdd(&g_cur[d], 1);
        g_csrc[pos] = s;
        g_cw[pos] = g_dis[s] * g_dis[d];
    }
}

// ---------------- TF32 tensor-core GEMM ----------------
// C[M,N] = A[M,K] @ B[K,N] (+ optional bias & leaky relu)
// Block tile: 128 x NT. 8 warps (4 m x 2 n). Warp tile: 32 x NT/2.
// K-chunk 32, register-prefetch double buffering.

__device__ __forceinline__ uint32_t f2tf32(float x) {
    uint32_t r;
    asm("cvt.rna.tf32.f32 %0, %1;" : "=r"(r) : "f"(x));
    return r;
}

#define MMA_TF32(d, a, b)                                                             \
    asm volatile(                                                                     \
        "mma.sync.aligned.m16n8k8.row.col.f32.tf32.tf32.f32 "                         \
        "{%0,%1,%2,%3}, {%4,%5,%6,%7}, {%8,%9}, {%0,%1,%2,%3};"                       \
        : "+f"((d)[0]), "+f"((d)[1]), "+f"((d)[2]), "+f"((d)[3])                      \
        : "r"((a)[0]), "r"((a)[1]), "r"((a)[2]), "r"((a)[3]), "r"((b)[0]), "r"((b)[1]))

template <int NT, bool BIAS_ACT>
__global__ __launch_bounds__(256) void gemm_tc_kernel(
    const float* __restrict__ A, const float* __restrict__ B,
    const float* __restrict__ bias, float* __restrict__ C,
    int M, int N, int K) {
    constexpr int NF = NT / 16;      // n-frags per warp
    constexpr int BS = NT + 4;       // padded B smem row stride
    constexpr int NB = NT / 32;      // B float4 loads per thread per chunk
    __shared__ uint32_t As[128 * 36];  // [m][k] stride 36 (32 + 4 pad)
    __shared__ uint32_t Bs[32 * BS];   // [k][n] stride BS

    const int tid = threadIdx.x;
    const int lane = tid & 31;
    const int wid = tid >> 5;
    const int wm = (wid & 3) * 32;
    const int wn = (wid >> 2) * (NT / 2);
    const int g = lane >> 2;
    const int t4 = lane & 3;
    const int bm = blockIdx.y * 128;
    const int bn = blockIdx.x * NT;

    // global load mappings (chunk = A:128x32, B:32xNT)
    const int aR = tid >> 3;            // will be extended by it*32? no: id-based below
    (void)aR;

    float c[2][NF][4] = {};
    float4 pa[4], pb[NB];

    // prefetch chunk 0
#pragma unroll
    for (int it = 0; it < 4; it++) {
        int id = it * 256 + tid;
        int r = id >> 3, cc = (id & 7) * 4;
        pa[it] = (bm + r < M) ? *(const float4*)(A + (size_t)(bm + r) * K + cc)
                              : make_float4(0.f, 0.f, 0.f, 0.f);
    }
#pragma unroll
    for (int it = 0; it < NB; it++) {
        int id = it * 256 + tid;
        int r = id / (NT / 4), cc = (id % (NT / 4)) * 4;
        pb[it] = *(const float4*)(B + (size_t)r * N + bn + cc);
    }

    for (int k0 = 0; k0 < K; k0 += 32) {
        // ---- store prefetched chunk to smem (with tf32 cvt) ----
#pragma unroll
        for (int it = 0; it < 4; it++) {
            int id = it * 256 + tid;
            int r = id >> 3, cc = (id & 7) * 4;
            uint32_t* p = &As[r * 36 + cc];
            p[0] = f2tf32(pa[it].x); p[1] = f2tf32(pa[it].y);
            p[2] = f2tf32(pa[it].z); p[3] = f2tf32(pa[it].w);
        }
#pragma unroll
        for (int it = 0; it < NB; it++) {
            int id = it * 256 + tid;
            int r = id / (NT / 4), cc = (id % (NT / 4)) * 4;
            uint32_t* p = &Bs[r * BS + cc];
            p[0] = f2tf32(pb[it].x); p[1] = f2tf32(pb[it].y);
            p[2] = f2tf32(pb[it].z); p[3] = f2tf32(pb[it].w);
        }
        __syncthreads();

        // ---- prefetch next chunk ----
        int kn = k0 + 32;
        if (kn < K) {
#pragma unroll
            for (int it = 0; it < 4; it++) {
                int id = it * 256 + tid;
                int r = id >> 3, cc = (id & 7) * 4;
                pa[it] = (bm + r < M) ? *(const float4*)(A + (size_t)(bm + r) * K + kn + cc)
                                      : make_float4(0.f, 0.f, 0.f, 0.f);
            }
#pragma unroll
            for (int it = 0; it < NB; it++) {
                int id = it * 256 + tid;
                int r = id / (NT / 4), cc = (id % (NT / 4)) * 4;
                pb[it] = *(const float4*)(B + (size_t)(kn + r) * N + bn + cc);
            }
        }

        // ---- MMA over 4 k-steps of 8 ----
#pragma unroll
        for (int s = 0; s < 4; s++) {
            uint32_t a[2][4];
#pragma unroll
            for (int mf = 0; mf < 2; mf++) {
                int r0 = (wm + mf * 16 + g) * 36 + s * 8 + t4;
                int r1 = (wm + mf * 16 + g + 8) * 36 + s * 8 + t4;
                a[mf][0] = As[r0];
                a[mf][1] = As[r1];
                a[mf][2] = As[r0 + 4];
                a[mf][3] = As[r1 + 4];
            }
            uint32_t b[NF][2];
#pragma unroll
            for (int nf = 0; nf < NF; nf++) {
                int col = wn + nf * 8 + g;
                b[nf][0] = Bs[(s * 8 + t4) * BS + col];
                b[nf][1] = Bs[(s * 8 + t4 + 4) * BS + col];
            }
#pragma unroll
            for (int mf = 0; mf < 2; mf++)
#pragma unroll
                for (int nf = 0; nf < NF; nf++) MMA_TF32(c[mf][nf], a[mf], b[nf]);
        }
        __syncthreads();
    }

    // ---- epilogue ----
#pragma unroll
    for (int mf = 0; mf < 2; mf++) {
        int r0 = bm + wm + mf * 16 + g;
        int r1 = r0 + 8;
#pragma unroll
        for (int nf = 0; nf < NF; nf++) {
            int col = bn + wn + nf * 8 + 2 * t4;
            float v0 = c[mf][nf][0], v1 = c[mf][nf][1];
            float v2 = c[mf][nf][2], v3 = c[mf][nf][3];
            if (BIAS_ACT) {
                float bb0 = bias[col], bb1 = bias[col + 1];
                v0 += bb0; v1 += bb1; v2 += bb0; v3 += bb1;
                v0 = v0 > 0.f ? v0 : 0.01f * v0;
                v1 = v1 > 0.f ? v1 : 0.01f * v1;
                v2 = v2 > 0.f ? v2 : 0.01f * v2;
                v3 = v3 > 0.f ? v3 : 0.01f * v3;
            }
            if (r0 < M) { float2 o; o.x = v0; o.y = v1; *(float2*)(C + (size_t)r0 * N + col) = o; }
            if (r1 < M) { float2 o; o.x = v2; o.y = v3; *(float2*)(C + (size_t)r1 * N + col) = o; }
        }
    }
}

// ---------------- gather aggregation: H = [lrelu](S·Y [+ b]) ----------------
// S = Dis^-1/2 (A+I) Dis^-1/2, CSR-by-dst gather, one warp per node.
template <int C, bool BIAS_ACT>
__global__ __launch_bounds__(256) void agg_kernel(
    const float* __restrict__ Y, const float* __restrict__ bias, float* __restrict__ H) {
    int node = (blockIdx.x * blockDim.x + threadIdx.x) >> 5;
    int lane = threadIdx.x & 31;
    if (node >= NN) return;

    float dn = g_dis[node];
    float selfw = dn * dn;
    int beg = g_off[node];
    int end = g_off[node + 1];

    if constexpr (C == 64) {
        const float2* yr = (const float2*)(Y + (size_t)node * 64);
        float2 v = yr[lane];
        float ax = selfw * v.x, ay = selfw * v.y;
        int i = beg;
        for (; i + 2 <= end; i += 2) {
            int s0 = g_csrc[i], s1 = g_csrc[i + 1];
            float w0 = g_cw[i], w1 = g_cw[i + 1];
            float2 u0 = ((const float2*)(Y + (size_t)s0 * 64))[lane];
            float2 u1 = ((const float2*)(Y + (size_t)s1 * 64))[lane];
            ax += w0 * u0.x + w1 * u1.x;
            ay += w0 * u0.y + w1 * u1.y;
        }
        if (i < end) {
            int s0 = g_csrc[i];
            float w0 = g_cw[i];
            float2 u0 = ((const float2*)(Y + (size_t)s0 * 64))[lane];
            ax += w0 * u0.x;
            ay += w0 * u0.y;
        }
        if (BIAS_ACT) {
            float2 b = ((const float2*)bias)[lane];
            ax += b.x; ay += b.y;
            ax = ax > 0.f ? ax : 0.01f * ax;
            ay = ay > 0.f ? ay : 0.01f * ay;
        }
        float2 o; o.x = ax; o.y = ay;
        ((float2*)(H + (size_t)node * 64))[lane] = o;
    } else {
        float4 acc;
        const float4* yr = (const float4*)(Y + (size_t)node * C);
        {
            float4 u = yr[lane];
            acc.x = selfw * u.x; acc.y = selfw * u.y;
            acc.z = selfw * u.z; acc.w = selfw * u.w;
        }
        int i = beg;
        for (; i + 2 <= end; i += 2) {
            int s0 = g_csrc[i], s1 = g_csrc[i + 1];
            float w0 = g_cw[i], w1 = g_cw[i + 1];
            float4 u0 = ((const float4*)(Y + (size_t)s0 * C))[lane];
            float4 u1 = ((const float4*)(Y + (size_t)s1 * C))[lane];
            acc.x += w0 * u0.x + w1 * u1.x;
            acc.y += w0 * u0.y + w1 * u1.y;
            acc.z += w0 * u0.z + w1 * u1.z;
            acc.w += w0 * u0.w + w1 * u1.w;
        }
        if (i < end) {
            int s0 = g_csrc[i];
            float w0 = g_cw[i];
            float4 u0 = ((const float4*)(Y + (size_t)s0 * C))[lane];
            acc.x += w0 * u0.x;
            acc.y += w0 * u0.y;
            acc.z += w0 * u0.z;
            acc.w += w0 * u0.w;
        }
        if (BIAS_ACT) {
            float4 b = ((const float4*)bias)[lane];
            acc.x += b.x; acc.y += b.y; acc.z += b.z; acc.w += b.w;
            acc.x = acc.x > 0.f ? acc.x : 0.01f * acc.x;
            acc.y = acc.y > 0.f ? acc.y : 0.01f * acc.y;
            acc.z = acc.z > 0.f ? acc.z : 0.01f * acc.z;
            acc.w = acc.w > 0.f ? acc.w : 0.01f * acc.w;
        }
        ((float4*)(H + (size_t)node * C))[lane] = acc;
    }
}

// ---------------- final projection: out = h3[N,64] @ W_out[64,1] + b_out ----------------
__global__ __launch_bounds__(256) void out_kernel(
    const float* __restrict__ H, const float* __restrict__ Wout,
    const float* __restrict__ bout, float* __restrict__ out) {
    int node = (blockIdx.x * blockDim.x + threadIdx.x) >> 5;
    int lane = threadIdx.x & 31;
    if (node >= NN) return;
    const float* h = H + (size_t)node * 64;
    float v = h[lane] * Wout[lane] + h[lane + 32] * Wout[lane + 32];
#pragma unroll
    for (int o = 16; o > 0; o >>= 1) v += __shfl_down_sync(0xffffffffu, v, o);
    if (lane == 0) out[node] = v + bout[0];
}

// ---------------- launch ----------------
extern "C" void kernel_launch(void* const* d_in, const int* in_sizes, int n_in,
                              void* d_out, int out_size) {
    const float* x    = (const float*)d_in[0];
    const int*   ei   = (const int*)d_in[1];
    const float* W_in = (const float*)d_in[2];
    const float* b_in = (const float*)d_in[3];
    const float* W1   = (const float*)d_in[4];
    const float* b1   = (const float*)d_in[5];
    const float* W2   = (const float*)d_in[6];
    const float* b2   = (const float*)d_in[7];
    const float* W3   = (const float*)d_in[8];
    const float* b3   = (const float*)d_in[9];
    const float* Wo   = (const float*)d_in[10];
    const float* bo   = (const float*)d_in[11];
    float* out = (float*)d_out;

    const int* src = ei;
    const int* dst = ei + EE;

    float *buf0, *buf1;
    cudaGetSymbolAddress((void**)&buf0, g_buf0);
    cudaGetSymbolAddress((void**)&buf1, g_buf1);

    // graph preprocessing (deg / dis / CSR-by-dst) — shared by all 3 conv layers
    zero_deg_kernel<<<(NN + 255) / 256, 256>>>();
    count_deg_kernel<<<(EE + 255) / 256, 256>>>(dst);
    scan_kernel<<<1, 1024>>>();
    fill_csr_kernel<<<(EE + 255) / 256, 256>>>(src, dst);

    const int MT = (NN + 127) / 128;
    const int AGG_GRID = (NN + 7) / 8;

    // h0 = lrelu(x @ W_in + b_in)                       [N,128]
    gemm_tc_kernel<128, true><<<dim3(1, MT), 256>>>(x, W_in, b_in, buf0, NN, 128, 128);
    // layer 1 (agg first: S·(h@W1) == (S·h)@W1):
    //   Z1 = S·h0                [N,128]
    agg_kernel<128, false><<<AGG_GRID, 256>>>(buf0, nullptr, buf1);
    //   h1 = lrelu(Z1 @ W1 + b1) [N,256]
    gemm_tc_kernel<128, true><<<dim3(2, MT), 256>>>(buf1, W1, b1, buf0, NN, 256, 128);
    // layer 2 (gemm first):
    //   Y2 = h1 @ W2             [N,128]
    gemm_tc_kernel<128, false><<<dim3(1, MT), 256>>>(buf0, W2, nullptr, buf1, NN, 128, 256);
    //   h2 = lrelu(S·Y2 + b2)    [N,128]
    agg_kernel<128, true><<<AGG_GRID, 256>>>(buf1, b2, buf0);
    // layer 3 (gemm first):
    //   Y3 = h2 @ W3             [N,64]
    gemm_tc_kernel<64, false><<<dim3(1, MT), 256>>>(buf0, W3, nullptr, buf1, NN, 64, 128);
    //   h3 = lrelu(S·Y3 + b3)    [N,64]
    agg_kernel<64, true><<<AGG_GRID, 256>>>(buf1, b3, buf0);
    // out = h3 @ W_out + b_out
    out_kernel<<<AGG_GRID, 256>>>(buf0, Wo, bo, out);
}

// round 5
// speedup vs baseline: 1.5951x; 1.0502x over previous
#include <cuda_runtime.h>
#include <cstdint>

#define NN 50000
#define EE 800000

// ---------------- scratch (static device globals; no allocation) ----------------
__device__ float g_buf0[NN * 256];
__device__ float g_buf1[NN * 256];
__device__ float g_dis[NN];
__device__ int   g_deg[NN];
__device__ int   g_off[NN + 1];
__device__ int   g_cur[NN];
__device__ int   g_csrc[EE];
__device__ float g_cw[EE];
// pre-rounded (tf32-representable) weights
__device__ float g_w0[128 * 128];
__device__ float g_w1[128 * 256];
__device__ float g_w2[256 * 128];
__device__ float g_w3[128 * 64];

__device__ __forceinline__ uint32_t f2tf32(float x) {
    uint32_t r;
    asm("cvt.rna.tf32.f32 %0, %1;" : "=r"(r) : "f"(x));
    return r;
}
__device__ __forceinline__ float tf32r(float x) { return __uint_as_float(f2tf32(x)); }

// ---------------- rounding copy (round-to-nearest tf32, stored as fp32) ----------------
__global__ void round_kernel(const float* __restrict__ src, float* __restrict__ dst, int n4) {
    int i = blockIdx.x * blockDim.x + threadIdx.x;
    if (i < n4) {
        float4 v = ((const float4*)src)[i];
        v.x = tf32r(v.x); v.y = tf32r(v.y); v.z = tf32r(v.z); v.w = tf32r(v.w);
        ((float4*)dst)[i] = v;
    }
}

// ---------------- graph preprocessing ----------------
__global__ void count_deg_kernel(const int* __restrict__ dst) {
    int e = blockIdx.x * blockDim.x + threadIdx.x;
    if (e < EE) atomicAdd(&g_deg[dst[e]], 1);
}

// Single-block exclusive scan over deg -> offsets; also dis = rsqrt(deg+1), cursor init.
__global__ void scan_kernel() {
    __shared__ int s[1024];
    const int t = threadIdx.x;
    const int CH = (NN + 1023) / 1024;  // 49
    int start = t * CH;
    int end = min(start + CH, NN);
    int sum = 0;
    for (int i = start; i < end; i++) sum += g_deg[i];
    s[t] = sum;
    __syncthreads();
    for (int off = 1; off < 1024; off <<= 1) {
        int v = (t >= off) ? s[t - off] : 0;
        __syncthreads();
        s[t] += v;
        __syncthreads();
    }
    int run = (t == 0) ? 0 : s[t - 1];
    for (int i = start; i < end; i++) {
        g_off[i] = run;
        g_cur[i] = run;
        g_dis[i] = rsqrtf((float)(g_deg[i] + 1));
        run += g_deg[i];
    }
    if (start < NN && end == NN) g_off[NN] = run;
}

__global__ void fill_csr_kernel(const int* __restrict__ src, const int* __restrict__ dst) {
    int e = blockIdx.x * blockDim.x + threadIdx.x;
    if (e < EE) {
        int s = src[e];
        int d = dst[e];
        int pos = atomicAdd(&g_cur[d], 1);
        g_csrc[pos] = s;
        g_cw[pos] = g_dis[s] * g_dis[d];
    }
}

// ---------------- TF32 tensor-core GEMM with cp.async pipeline ----------------
// C[M,N] = A[M,K] @ B[K,N] (+ optional bias & leaky relu, optional tf32-rounded store)
// Inputs A,B MUST already be tf32-representable (low 13 mantissa bits zero), so the
// HW mantissa truncation inside mma.tf32 is exact.
// Block tile: 128 x NT. 8 warps (4 m x 2 n). K-chunk 32, 2-stage cp.async.

#define MMA_TF32(d, a, b)                                                             \
    asm volatile(                                                                     \
        "mma.sync.aligned.m16n8k8.row.col.f32.tf32.tf32.f32 "                         \
        "{%0,%1,%2,%3}, {%4,%5,%6,%7}, {%8,%9}, {%0,%1,%2,%3};"                       \
        : "+f"((d)[0]), "+f"((d)[1]), "+f"((d)[2]), "+f"((d)[3])                      \
        : "r"((a)[0]), "r"((a)[1]), "r"((a)[2]), "r"((a)[3]), "r"((b)[0]), "r"((b)[1]))

__device__ __forceinline__ void cp_async16(uint32_t smem_addr, const void* gptr) {
    asm volatile("cp.async.cg.shared.global [%0], [%1], 16;\n" ::"r"(smem_addr), "l"(gptr));
}
__device__ __forceinline__ void cp_commit() { asm volatile("cp.async.commit_group;\n"); }
template <int W>
__device__ __forceinline__ void cp_wait() { asm volatile("cp.async.wait_group %0;\n" ::"n"(W)); }

template <int NT, bool BIAS_ACT, bool ROUND>
__global__ __launch_bounds__(256) void gemm_tc_kernel(
    const float* __restrict__ A, const float* __restrict__ B,
    const float* __restrict__ bias, float* __restrict__ C,
    int M, int N, int K) {
    constexpr int NF = NT / 16;      // n-frags per warp
    constexpr int BS = NT + 4;       // padded B smem row stride (uints)
    constexpr int NB = NT / 32;      // B 16B-loads per thread per chunk
    __shared__ uint32_t As[2][128 * 36];  // [m][k] stride 36 (32 + 4 pad)
    __shared__ uint32_t Bs[2][32 * BS];   // [k][n] stride BS

    const int tid = threadIdx.x;
    const int lane = tid & 31;
    const int wid = tid >> 5;
    const int wm = (wid & 3) * 32;
    const int wn = (wid >> 2) * (NT / 2);
    const int g = lane >> 2;
    const int t4 = lane & 3;
    const int bm = blockIdx.y * 128;
    const int bn = blockIdx.x * NT;

    // per-thread load coordinates (16B granularity)
    const int aR = tid >> 3;           // base row 0..31 (x4 iterations of 32 rows)
    const int aC = (tid & 7) * 4;      // k-col 0,4,..,28
    const int bR = tid / (NT / 4);     // base k-row
    const int bC = (tid % (NT / 4)) * 4;

    auto issue_chunk = [&](int k0, int st) {
#pragma unroll
        for (int it = 0; it < 4; it++) {
            int r = it * 32 + aR;
            int gr = min(bm + r, M - 1);  // clamp: garbage rows only affect discarded C rows
            uint32_t da = (uint32_t)__cvta_generic_to_shared(&As[st][r * 36 + aC]);
            cp_async16(da, A + (size_t)gr * K + k0 + aC);
        }
        constexpr int RPI = 256 / (NT / 4);  // k-rows covered per iteration
#pragma unroll
        for (int it = 0; it < NB; it++) {
            int r = it * RPI + bR;
            uint32_t db = (uint32_t)__cvta_generic_to_shared(&Bs[st][r * BS + bC]);
            cp_async16(db, B + (size_t)(k0 + r) * N + bn + bC);
        }
        cp_commit();
    };

    float c[2][NF][4] = {};

    const int nch = K >> 5;
    issue_chunk(0, 0);

    for (int i = 0; i < nch; i++) {
        const int st = i & 1;
        if (i + 1 < nch) {
            issue_chunk((i + 1) << 5, st ^ 1);
            cp_wait<1>();
        } else {
            cp_wait<0>();
        }
        __syncthreads();

#pragma unroll
        for (int s = 0; s < 4; s++) {
            uint32_t a[2][4];
#pragma unroll
            for (int mf = 0; mf < 2; mf++) {
                int r0 = (wm + mf * 16 + g) * 36 + s * 8 + t4;
                int r1 = (wm + mf * 16 + g + 8) * 36 + s * 8 + t4;
                a[mf][0] = As[st][r0];
                a[mf][1] = As[st][r1];
                a[mf][2] = As[st][r0 + 4];
                a[mf][3] = As[st][r1 + 4];
            }
            uint32_t b[NF][2];
#pragma unroll
            for (int nf = 0; nf < NF; nf++) {
                int col = wn + nf * 8 + g;
                b[nf][0] = Bs[st][(s * 8 + t4) * BS + col];
                b[nf][1] = Bs[st][(s * 8 + t4 + 4) * BS + col];
            }
#pragma unroll
            for (int mf = 0; mf < 2; mf++)
#pragma unroll
                for (int nf = 0; nf < NF; nf++) MMA_TF32(c[mf][nf], a[mf], b[nf]);
        }
        __syncthreads();  // protect stage st from next issue
    }

    // ---- epilogue ----
#pragma unroll
    for (int mf = 0; mf < 2; mf++) {
        int r0 = bm + wm + mf * 16 + g;
        int r1 = r0 + 8;
#pragma unroll
        for (int nf = 0; nf < NF; nf++) {
            int col = bn + wn + nf * 8 + 2 * t4;
            float v0 = c[mf][nf][0], v1 = c[mf][nf][1];
            float v2 = c[mf][nf][2], v3 = c[mf][nf][3];
            if (BIAS_ACT) {
                float bb0 = bias[col], bb1 = bias[col + 1];
                v0 += bb0; v1 += bb1; v2 += bb0; v3 += bb1;
                v0 = v0 > 0.f ? v0 : 0.01f * v0;
                v1 = v1 > 0.f ? v1 : 0.01f * v1;
                v2 = v2 > 0.f ? v2 : 0.01f * v2;
                v3 = v3 > 0.f ? v3 : 0.01f * v3;
            }
            if (ROUND) {  // next consumer is a GEMM: store tf32-representable
                v0 = tf32r(v0); v1 = tf32r(v1); v2 = tf32r(v2); v3 = tf32r(v3);
            }
            if (r0 < M) { float2 o; o.x = v0; o.y = v1; *(float2*)(C + (size_t)r0 * N + col) = o; }
            if (r1 < M) { float2 o; o.x = v2; o.y = v3; *(float2*)(C + (size_t)r1 * N + col) = o; }
        }
    }
}

// ---------------- gather aggregation: H = [lrelu](S·Y [+ b]) ----------------
// S = Dis^-1/2 (A+I) Dis^-1/2, CSR-by-dst gather, one warp per node. 4x unroll.
template <int C, bool BIAS_ACT, bool ROUND>
__global__ __launch_bounds__(256) void agg_kernel(
    const float* __restrict__ Y, const float* __restrict__ bias, float* __restrict__ H) {
    int node = (blockIdx.x * blockDim.x + threadIdx.x) >> 5;
    int lane = threadIdx.x & 31;
    if (node >= NN) return;

    float dn = g_dis[node];
    float selfw = dn * dn;
    int beg = g_off[node];
    int end = g_off[node + 1];

    float4 acc;
    const float4* yr = (const float4*)(Y + (size_t)node * C);
    {
        float4 u = yr[lane];
        acc.x = selfw * u.x; acc.y = selfw * u.y;
        acc.z = selfw * u.z; acc.w = selfw * u.w;
    }
    int i = beg;
    for (; i + 4 <= end; i += 4) {
        int s0 = g_csrc[i], s1 = g_csrc[i + 1], s2 = g_csrc[i + 2], s3 = g_csrc[i + 3];
        float w0 = g_cw[i], w1 = g_cw[i + 1], w2 = g_cw[i + 2], w3 = g_cw[i + 3];
        float4 u0 = ((const float4*)(Y + (size_t)s0 * C))[lane];
        float4 u1 = ((const float4*)(Y + (size_t)s1 * C))[lane];
        float4 u2 = ((const float4*)(Y + (size_t)s2 * C))[lane];
        float4 u3 = ((const float4*)(Y + (size_t)s3 * C))[lane];
        acc.x += w0 * u0.x + w1 * u1.x + w2 * u2.x + w3 * u3.x;
        acc.y += w0 * u0.y + w1 * u1.y + w2 * u2.y + w3 * u3.y;
        acc.z += w0 * u0.z + w1 * u1.z + w2 * u2.z + w3 * u3.z;
        acc.w += w0 * u0.w + w1 * u1.w + w2 * u2.w + w3 * u3.w;
    }
    for (; i < end; i++) {
        int s0 = g_csrc[i];
        float w0 = g_cw[i];
        float4 u0 = ((const float4*)(Y + (size_t)s0 * C))[lane];
        acc.x += w0 * u0.x;
        acc.y += w0 * u0.y;
        acc.z += w0 * u0.z;
        acc.w += w0 * u0.w;
    }
    if (BIAS_ACT) {
        float4 b = ((const float4*)bias)[lane];
        acc.x += b.x; acc.y += b.y; acc.z += b.z; acc.w += b.w;
        acc.x = acc.x > 0.f ? acc.x : 0.01f * acc.x;
        acc.y = acc.y > 0.f ? acc.y : 0.01f * acc.y;
        acc.z = acc.z > 0.f ? acc.z : 0.01f * acc.z;
        acc.w = acc.w > 0.f ? acc.w : 0.01f * acc.w;
    }
    if (ROUND) {  // next consumer is a GEMM
        acc.x = tf32r(acc.x); acc.y = tf32r(acc.y);
        acc.z = tf32r(acc.z); acc.w = tf32r(acc.w);
    }
    ((float4*)(H + (size_t)node * C))[lane] = acc;
}

// ---------------- final agg (C=64) fused with output projection ----------------
// out[node] = lrelu(S·Y3 + b3) · W_out + b_out   — h3 never hits memory.
__global__ __launch_bounds__(256) void agg64_out_kernel(
    const float* __restrict__ Y, const float* __restrict__ bias,
    const float* __restrict__ Wout, const float* __restrict__ bout,
    float* __restrict__ out) {
    int node = (blockIdx.x * blockDim.x + threadIdx.x) >> 5;
    int lane = threadIdx.x & 31;
    if (node >= NN) return;

    float dn = g_dis[node];
    float selfw = dn * dn;
    int beg = g_off[node];
    int end = g_off[node + 1];

    float2 acc;
    {
        float2 u = ((const float2*)(Y + (size_t)node * 64))[lane];
        acc.x = selfw * u.x;
        acc.y = selfw * u.y;
    }
    int i = beg;
    for (; i + 4 <= end; i += 4) {
        int s0 = g_csrc[i], s1 = g_csrc[i + 1], s2 = g_csrc[i + 2], s3 = g_csrc[i + 3];
        float w0 = g_cw[i], w1 = g_cw[i + 1], w2 = g_cw[i + 2], w3 = g_cw[i + 3];
        float2 u0 = ((const float2*)(Y + (size_t)s0 * 64))[lane];
        float2 u1 = ((const float2*)(Y + (size_t)s1 * 64))[lane];
        float2 u2 = ((const float2*)(Y + (size_t)s2 * 64))[lane];
        float2 u3 = ((const float2*)(Y + (size_t)s3 * 64))[lane];
        acc.x += w0 * u0.x + w1 * u1.x + w2 * u2.x + w3 * u3.x;
        acc.y += w0 * u0.y + w1 * u1.y + w2 * u2.y + w3 * u3.y;
    }
    for (; i < end; i++) {
        int s0 = g_csrc[i];
        float w0 = g_cw[i];
        float2 u0 = ((const float2*)(Y + (size_t)s0 * 64))[lane];
        acc.x += w0 * u0.x;
        acc.y += w0 * u0.y;
    }
    float2 b = ((const float2*)bias)[lane];
    acc.x += b.x; acc.y += b.y;
    acc.x = acc.x > 0.f ? acc.x : 0.01f * acc.x;
    acc.y = acc.y > 0.f ? acc.y : 0.01f * acc.y;

    float2 w = ((const float2*)Wout)[lane];
    float v = acc.x * w.x + acc.y * w.y;
#pragma unroll
    for (int o = 16; o > 0; o >>= 1) v += __shfl_down_sync(0xffffffffu, v, o);
    if (lane == 0) out[node] = v + bout[0];
}

// ---------------- launch ----------------
extern "C" void kernel_launch(void* const* d_in, const int* in_sizes, int n_in,
                              void* d_out, int out_size) {
    const float* x    = (const float*)d_in[0];
    const int*   ei   = (const int*)d_in[1];
    const float* W_in = (const float*)d_in[2];
    const float* b_in = (const float*)d_in[3];
    const float* W1   = (const float*)d_in[4];
    const float* b1   = (const float*)d_in[5];
    const float* W2   = (const float*)d_in[6];
    const float* b2   = (const float*)d_in[7];
    const float* W3   = (const float*)d_in[8];
    const float* b3   = (const float*)d_in[9];
    const float* Wo   = (const float*)d_in[10];
    const float* bo   = (const float*)d_in[11];
    float* out = (float*)d_out;

    const int* src = ei;
    const int* dst = ei + EE;

    float *buf0, *buf1, *w0, *w1, *w2, *w3;
    cudaGetSymbolAddress((void**)&buf0, g_buf0);
    cudaGetSymbolAddress((void**)&buf1, g_buf1);
    cudaGetSymbolAddress((void**)&w0, g_w0);
    cudaGetSymbolAddress((void**)&w1, g_w1);
    cudaGetSymbolAddress((void**)&w2, g_w2);
    cudaGetSymbolAddress((void**)&w3, g_w3);
    int* degp;
    cudaGetSymbolAddress((void**)&degp, g_deg);

    // graph preprocessing (deg / dis / CSR-by-dst) — shared by all 3 conv layers
    cudaMemsetAsync(degp, 0, NN * sizeof(int));
    count_deg_kernel<<<(EE + 255) / 256, 256>>>(dst);
    scan_kernel<<<1, 1024>>>();
    fill_csr_kernel<<<(EE + 255) / 256, 256>>>(src, dst);

    // round-to-nearest tf32 for all GEMM inputs (so cp.async + HW-truncate is exact)
    round_kernel<<<(128 * 128 / 4 + 255) / 256, 256>>>(W_in, w0, 128 * 128 / 4);
    round_kernel<<<(128 * 256 / 4 + 255) / 256, 256>>>(W1, w1, 128 * 256 / 4);
    round_kernel<<<(256 * 128 / 4 + 255) / 256, 256>>>(W2, w2, 256 * 128 / 4);
    round_kernel<<<(128 * 64 / 4 + 255) / 256, 256>>>(W3, w3, 128 * 64 / 4);
    round_kernel<<<(NN * 128 / 4 + 255) / 256, 256>>>(x, buf1, NN * 128 / 4);

    const int MT = (NN + 127) / 128;
    const int AGG_GRID = (NN + 7) / 8;

    // h0 = lrelu(x @ W_in + b_in), rounded                 [N,128]
    gemm_tc_kernel<128, true, true><<<dim3(1, MT), 256>>>(buf1, w0, b_in, buf0, NN, 128, 128);
    // layer 1 (agg first: S·(h@W1) == (S·h)@W1):
    agg_kernel<128, false, true><<<AGG_GRID, 256>>>(buf0, nullptr, buf1);   // Z1 = S·h0, rounded
    gemm_tc_kernel<128, true, true><<<dim3(2, MT), 256>>>(buf1, w1, b1, buf0, NN, 256, 128);  // h1
    // layer 2 (gemm first):
    gemm_tc_kernel<128, false, false><<<dim3(1, MT), 256>>>(buf0, w2, nullptr, buf1, NN, 128, 256);  // Y2
    agg_kernel<128, true, true><<<AGG_GRID, 256>>>(buf1, b2, buf0);         // h2, rounded
    // layer 3 (gemm first):
    gemm_tc_kernel<64, false, false><<<dim3(1, MT), 256>>>(buf0, w3, nullptr, buf1, NN, 64, 128);    // Y3
    // h3 = lrelu(S·Y3 + b3); out = h3 @ W_out + b_out  (fused)
    agg64_out_kernel<<<AGG_GRID, 256>>>(buf1, b3, Wo, bo, out);
}

// round 6
// speedup vs baseline: 1.7085x; 1.0711x over previous
#include <cuda_runtime.h>
#include <cstdint>

#define NN 50000
#define EE 800000

// ---------------- scratch (static device globals; no allocation) ----------------
__device__ float g_buf0[NN * 256];
__device__ float g_buf1[NN * 256];
__device__ float g_dis[NN];
__device__ int   g_deg[NN];
__device__ int   g_off[NN + 1];
__device__ int   g_cur[NN];
__device__ int   g_csrc[EE];
__device__ float g_cw[EE];
// pre-rounded (tf32-representable) weights
__device__ float g_w0[128 * 128];
__device__ float g_w1[128 * 256];
__device__ float g_w2[256 * 128];
__device__ float g_w3[128 * 64];

__device__ __forceinline__ uint32_t f2tf32(float x) {
    uint32_t r;
    asm("cvt.rna.tf32.f32 %0, %1;" : "=r"(r) : "f"(x));
    return r;
}
__device__ __forceinline__ float tf32r(float x) { return __uint_as_float(f2tf32(x)); }

// ---------------- fused rounding copy: x -> xr, 4 weight tensors -> globals ----------------
#define XF4  (NN * 128 / 4)      // 1,600,000 float4
#define W0F4 (128 * 128 / 4)     // 4096
#define W1F4 (128 * 256 / 4)     // 8192
#define W2F4 (256 * 128 / 4)     // 8192
#define W3F4 (128 * 64 / 4)      // 2048
#define RTOT (XF4 + W0F4 + W1F4 + W2F4 + W3F4)

__global__ void round_all_kernel(
    const float* __restrict__ x, const float* __restrict__ Wi,
    const float* __restrict__ W1, const float* __restrict__ W2,
    const float* __restrict__ W3, float* __restrict__ xr) {
    int i = blockIdx.x * blockDim.x + threadIdx.x;
    if (i >= RTOT) return;
    const float4* s;
    float4* d;
    int j;
    if (i < XF4) { s = (const float4*)x; d = (float4*)xr; j = i; }
    else if (i < XF4 + W0F4) { s = (const float4*)Wi; d = (float4*)g_w0; j = i - XF4; }
    else if (i < XF4 + W0F4 + W1F4) { s = (const float4*)W1; d = (float4*)g_w1; j = i - XF4 - W0F4; }
    else if (i < XF4 + W0F4 + W1F4 + W2F4) { s = (const float4*)W2; d = (float4*)g_w2; j = i - XF4 - W0F4 - W1F4; }
    else { s = (const float4*)W3; d = (float4*)g_w3; j = i - XF4 - W0F4 - W1F4 - W2F4; }
    float4 v = s[j];
    v.x = tf32r(v.x); v.y = tf32r(v.y); v.z = tf32r(v.z); v.w = tf32r(v.w);
    d[j] = v;
}

// ---------------- graph preprocessing ----------------
__global__ void count_deg_kernel(const int* __restrict__ dst) {
    int e = blockIdx.x * blockDim.x + threadIdx.x;
    if (e < EE) atomicAdd(&g_deg[dst[e]], 1);
}

// Single-block exclusive scan over deg -> offsets; also dis = rsqrt(deg+1), cursor init.
__global__ void scan_kernel() {
    __shared__ int s[1024];
    const int t = threadIdx.x;
    const int CH = (NN + 1023) / 1024;  // 49
    int start = t * CH;
    int end = min(start + CH, NN);
    int sum = 0;
    for (int i = start; i < end; i++) sum += g_deg[i];
    s[t] = sum;
    __syncthreads();
    for (int off = 1; off < 1024; off <<= 1) {
        int v = (t >= off) ? s[t - off] : 0;
        __syncthreads();
        s[t] += v;
        __syncthreads();
    }
    int run = (t == 0) ? 0 : s[t - 1];
    for (int i = start; i < end; i++) {
        g_off[i] = run;
        g_cur[i] = run;
        g_dis[i] = rsqrtf((float)(g_deg[i] + 1));
        run += g_deg[i];
    }
    if (start < NN && end == NN) g_off[NN] = run;
}

__global__ void fill_csr_kernel(const int* __restrict__ src, const int* __restrict__ dst) {
    int e = blockIdx.x * blockDim.x + threadIdx.x;
    if (e < EE) {
        int s = src[e];
        int d = dst[e];
        int pos = atomicAdd(&g_cur[d], 1);
        g_csrc[pos] = s;
        g_cw[pos] = g_dis[s] * g_dis[d];
    }
}

// ---------------- TF32 tensor-core GEMM with cp.async pipeline ----------------
// Inputs A,B MUST already be tf32-representable; HW truncation inside mma.tf32 is then exact.
// Block tile: 128 x NT. 8 warps (4 m x 2 n). K-chunk 32, 2-stage cp.async.

#define MMA_TF32(d, a, b)                                                             \
    asm volatile(                                                                     \
        "mma.sync.aligned.m16n8k8.row.col.f32.tf32.tf32.f32 "                         \
        "{%0,%1,%2,%3}, {%4,%5,%6,%7}, {%8,%9}, {%0,%1,%2,%3};"                       \
        : "+f"((d)[0]), "+f"((d)[1]), "+f"((d)[2]), "+f"((d)[3])                      \
        : "r"((a)[0]), "r"((a)[1]), "r"((a)[2]), "r"((a)[3]), "r"((b)[0]), "r"((b)[1]))

__device__ __forceinline__ void cp_async16(uint32_t smem_addr, const void* gptr) {
    asm volatile("cp.async.cg.shared.global [%0], [%1], 16;\n" ::"r"(smem_addr), "l"(gptr));
}
__device__ __forceinline__ void cp_commit() { asm volatile("cp.async.commit_group;\n"); }
template <int W>
__device__ __forceinline__ void cp_wait() { asm volatile("cp.async.wait_group %0;\n" ::"n"(W)); }

template <int NT, bool BIAS_ACT, bool ROUND>
__global__ __launch_bounds__(256) void gemm_tc_kernel(
    const float* __restrict__ A, const float* __restrict__ B,
    const float* __restrict__ bias, float* __restrict__ C,
    int M, int N, int K) {
    constexpr int NF = NT / 16;
    constexpr int BS = NT + 4;
    constexpr int NB = NT / 32;
    __shared__ uint32_t As[2][128 * 36];
    __shared__ uint32_t Bs[2][32 * BS];

    const int tid = threadIdx.x;
    const int lane = tid & 31;
    const int wid = tid >> 5;
    const int wm = (wid & 3) * 32;
    const int wn = (wid >> 2) * (NT / 2);
    const int g = lane >> 2;
    const int t4 = lane & 3;
    const int bm = blockIdx.y * 128;
    const int bn = blockIdx.x * NT;

    const int aR = tid >> 3;
    const int aC = (tid & 7) * 4;
    const int bR = tid / (NT / 4);
    const int bC = (tid % (NT / 4)) * 4;

    auto issue_chunk = [&](int k0, int st) {
#pragma unroll
        for (int it = 0; it < 4; it++) {
            int r = it * 32 + aR;
            int gr = min(bm + r, M - 1);
            uint32_t da = (uint32_t)__cvta_generic_to_shared(&As[st][r * 36 + aC]);
            cp_async16(da, A + (size_t)gr * K + k0 + aC);
        }
        constexpr int RPI = 256 / (NT / 4);
#pragma unroll
        for (int it = 0; it < NB; it++) {
            int r = it * RPI + bR;
            uint32_t db = (uint32_t)__cvta_generic_to_shared(&Bs[st][r * BS + bC]);
            cp_async16(db, B + (size_t)(k0 + r) * N + bn + bC);
        }
        cp_commit();
    };

    float c[2][NF][4] = {};

    const int nch = K >> 5;
    issue_chunk(0, 0);

    for (int i = 0; i < nch; i++) {
        const int st = i & 1;
        if (i + 1 < nch) {
            issue_chunk((i + 1) << 5, st ^ 1);
            cp_wait<1>();
        } else {
            cp_wait<0>();
        }
        __syncthreads();

#pragma unroll
        for (int s = 0; s < 4; s++) {
            uint32_t a[2][4];
#pragma unroll
            for (int mf = 0; mf < 2; mf++) {
                int r0 = (wm + mf * 16 + g) * 36 + s * 8 + t4;
                int r1 = (wm + mf * 16 + g + 8) * 36 + s * 8 + t4;
                a[mf][0] = As[st][r0];
                a[mf][1] = As[st][r1];
                a[mf][2] = As[st][r0 + 4];
                a[mf][3] = As[st][r1 + 4];
            }
            uint32_t b[NF][2];
#pragma unroll
            for (int nf = 0; nf < NF; nf++) {
                int col = wn + nf * 8 + g;
                b[nf][0] = Bs[st][(s * 8 + t4) * BS + col];
                b[nf][1] = Bs[st][(s * 8 + t4 + 4) * BS + col];
            }
#pragma unroll
            for (int mf = 0; mf < 2; mf++)
#pragma unroll
                for (int nf = 0; nf < NF; nf++) MMA_TF32(c[mf][nf], a[mf], b[nf]);
        }
        __syncthreads();
    }

#pragma unroll
    for (int mf = 0; mf < 2; mf++) {
        int r0 = bm + wm + mf * 16 + g;
        int r1 = r0 + 8;
#pragma unroll
        for (int nf = 0; nf < NF; nf++) {
            int col = bn + wn + nf * 8 + 2 * t4;
            float v0 = c[mf][nf][0], v1 = c[mf][nf][1];
            float v2 = c[mf][nf][2], v3 = c[mf][nf][3];
            if (BIAS_ACT) {
                float bb0 = bias[col], bb1 = bias[col + 1];
                v0 += bb0; v1 += bb1; v2 += bb0; v3 += bb1;
                v0 = v0 > 0.f ? v0 : 0.01f * v0;
                v1 = v1 > 0.f ? v1 : 0.01f * v1;
                v2 = v2 > 0.f ? v2 : 0.01f * v2;
                v3 = v3 > 0.f ? v3 : 0.01f * v3;
            }
            if (ROUND) {
                v0 = tf32r(v0); v1 = tf32r(v1); v2 = tf32r(v2); v3 = tf32r(v3);
            }
            if (r0 < M) { float2 o; o.x = v0; o.y = v1; *(float2*)(C + (size_t)r0 * N + col) = o; }
            if (r1 < M) { float2 o; o.x = v2; o.y = v3; *(float2*)(C + (size_t)r1 * N + col) = o; }
        }
    }
}

// ---------------- gather aggregation: H = [lrelu](S·Y [+ b]) ----------------
template <int C, bool BIAS_ACT, bool ROUND>
__global__ __launch_bounds__(256) void agg_kernel(
    const float* __restrict__ Y, const float* __restrict__ bias, float* __restrict__ H) {
    int node = (blockIdx.x * blockDim.x + threadIdx.x) >> 5;
    int lane = threadIdx.x & 31;
    if (node >= NN) return;

    float dn = g_dis[node];
    float selfw = dn * dn;
    int beg = g_off[node];
    int end = g_off[node + 1];

    float4 acc;
    const float4* yr = (const float4*)(Y + (size_t)node * C);
    {
        float4 u = yr[lane];
        acc.x = selfw * u.x; acc.y = selfw * u.y;
        acc.z = selfw * u.z; acc.w = selfw * u.w;
    }
    int i = beg;
    for (; i + 4 <= end; i += 4) {
        int s0 = g_csrc[i], s1 = g_csrc[i + 1], s2 = g_csrc[i + 2], s3 = g_csrc[i + 3];
        float w0 = g_cw[i], w1 = g_cw[i + 1], w2 = g_cw[i + 2], w3 = g_cw[i + 3];
        float4 u0 = ((const float4*)(Y + (size_t)s0 * C))[lane];
        float4 u1 = ((const float4*)(Y + (size_t)s1 * C))[lane];
        float4 u2 = ((const float4*)(Y + (size_t)s2 * C))[lane];
        float4 u3 = ((const float4*)(Y + (size_t)s3 * C))[lane];
        acc.x += w0 * u0.x + w1 * u1.x + w2 * u2.x + w3 * u3.x;
        acc.y += w0 * u0.y + w1 * u1.y + w2 * u2.y + w3 * u3.y;
        acc.z += w0 * u0.z + w1 * u1.z + w2 * u2.z + w3 * u3.z;
        acc.w += w0 * u0.w + w1 * u1.w + w2 * u2.w + w3 * u3.w;
    }
    for (; i < end; i++) {
        int s0 = g_csrc[i];
        float w0 = g_cw[i];
        float4 u0 = ((const float4*)(Y + (size_t)s0 * C))[lane];
        acc.x += w0 * u0.x;
        acc.y += w0 * u0.y;
        acc.z += w0 * u0.z;
        acc.w += w0 * u0.w;
    }
    if (BIAS_ACT) {
        float4 b = ((const float4*)bias)[lane];
        acc.x += b.x; acc.y += b.y; acc.z += b.z; acc.w += b.w;
        acc.x = acc.x > 0.f ? acc.x : 0.01f * acc.x;
        acc.y = acc.y > 0.f ? acc.y : 0.01f * acc.y;
        acc.z = acc.z > 0.f ? acc.z : 0.01f * acc.z;
        acc.w = acc.w > 0.f ? acc.w : 0.01f * acc.w;
    }
    if (ROUND) {
        acc.x = tf32r(acc.x); acc.y = tf32r(acc.y);
        acc.z = tf32r(acc.z); acc.w = tf32r(acc.w);
    }
    ((float4*)(H + (size_t)node * C))[lane] = acc;
}

// ---------------- final agg (C=64) fused with output projection ----------------
__global__ __launch_bounds__(256) void agg64_out_kernel(
    const float* __restrict__ Y, const float* __restrict__ bias,
    const float* __restrict__ Wout, const float* __restrict__ bout,
    float* __restrict__ out) {
    int node = (blockIdx.x * blockDim.x + threadIdx.x) >> 5;
    int lane = threadIdx.x & 31;
    if (node >= NN) return;

    float dn = g_dis[node];
    float selfw = dn * dn;
    int beg = g_off[node];
    int end = g_off[node + 1];

    float2 acc;
    {
        float2 u = ((const float2*)(Y + (size_t)node * 64))[lane];
        acc.x = selfw * u.x;
        acc.y = selfw * u.y;
    }
    int i = beg;
    for (; i + 4 <= end; i += 4) {
        int s0 = g_csrc[i], s1 = g_csrc[i + 1], s2 = g_csrc[i + 2], s3 = g_csrc[i + 3];
        float w0 = g_cw[i], w1 = g_cw[i + 1], w2 = g_cw[i + 2], w3 = g_cw[i + 3];
        float2 u0 = ((const float2*)(Y + (size_t)s0 * 64))[lane];
        float2 u1 = ((const float2*)(Y + (size_t)s1 * 64))[lane];
        float2 u2 = ((const float2*)(Y + (size_t)s2 * 64))[lane];
        float2 u3 = ((const float2*)(Y + (size_t)s3 * 64))[lane];
        acc.x += w0 * u0.x + w1 * u1.x + w2 * u2.x + w3 * u3.x;
        acc.y += w0 * u0.y + w1 * u1.y + w2 * u2.y + w3 * u3.y;
    }
    for (; i < end; i++) {
        int s0 = g_csrc[i];
        float w0 = g_cw[i];
        float2 u0 = ((const float2*)(Y + (size_t)s0 * 64))[lane];
        acc.x += w0 * u0.x;
        acc.y += w0 * u0.y;
    }
    float2 b = ((const float2*)bias)[lane];
    acc.x += b.x; acc.y += b.y;
    acc.x = acc.x > 0.f ? acc.x : 0.01f * acc.x;
    acc.y = acc.y > 0.f ? acc.y : 0.01f * acc.y;

    float2 w = ((const float2*)Wout)[lane];
    float v = acc.x * w.x + acc.y * w.y;
#pragma unroll
    for (int o = 16; o > 0; o >>= 1) v += __shfl_down_sync(0xffffffffu, v, o);
    if (lane == 0) out[node] = v + bout[0];
}

// ---------------- launch ----------------
extern "C" void kernel_launch(void* const* d_in, const int* in_sizes, int n_in,
                              void* d_out, int out_size) {
    const float* x    = (const float*)d_in[0];
    const int*   ei   = (const int*)d_in[1];
    const float* W_in = (const float*)d_in[2];
    const float* b_in = (const float*)d_in[3];
    const float* W1   = (const float*)d_in[4];
    const float* b1   = (const float*)d_in[5];
    const float* W2   = (const float*)d_in[6];
    const float* b2   = (const float*)d_in[7];
    const float* W3   = (const float*)d_in[8];
    const float* b3   = (const float*)d_in[9];
    const float* Wo   = (const float*)d_in[10];
    const float* bo   = (const float*)d_in[11];
    float* out = (float*)d_out;

    const int* src = ei;
    const int* dst = ei + EE;

    float *buf0, *buf1, *w0, *w1, *w2, *w3;
    cudaGetSymbolAddress((void**)&buf0, g_buf0);
    cudaGetSymbolAddress((void**)&buf1, g_buf1);
    cudaGetSymbolAddress((void**)&w0, g_w0);
    cudaGetSymbolAddress((void**)&w1, g_w1);
    cudaGetSymbolAddress((void**)&w2, g_w2);
    cudaGetSymbolAddress((void**)&w3, g_w3);
    int* degp;
    cudaGetSymbolAddress((void**)&degp, g_deg);

    // lazily created side-stream + events (host resources only; no device memory)
    static cudaStream_t s2 = nullptr;
    static cudaEvent_t ev_fork = nullptr, ev_join = nullptr;
    if (s2 == nullptr) {
        cudaStreamCreateWithFlags(&s2, cudaStreamNonBlocking);
        cudaEventCreateWithFlags(&ev_fork, cudaEventDisableTiming);
        cudaEventCreateWithFlags(&ev_join, cudaEventDisableTiming);
    }

    // ---- fork: preprocessing on s2, concurrent with round+gemm0 on main stream ----
    cudaEventRecord(ev_fork, 0);
    cudaStreamWaitEvent(s2, ev_fork, 0);

    cudaMemsetAsync(degp, 0, NN * sizeof(int), s2);
    count_deg_kernel<<<(EE + 255) / 256, 256, 0, s2>>>(dst);
    scan_kernel<<<1, 1024, 0, s2>>>();
    fill_csr_kernel<<<(EE + 255) / 256, 256, 0, s2>>>(src, dst);
    cudaEventRecord(ev_join, s2);

    // main stream: tf32 rounding (x -> buf1, weights -> g_w*) then gemm0
    round_all_kernel<<<(RTOT + 255) / 256, 256>>>(x, W_in, W1, W2, W3, buf1);

    const int MT = (NN + 127) / 128;
    const int AGG_GRID = (NN + 7) / 8;

    // h0 = lrelu(x @ W_in + b_in), rounded                 [N,128]
    gemm_tc_kernel<128, true, true><<<dim3(1, MT), 256>>>(buf1, w0, b_in, buf0, NN, 128, 128);

    // ---- join: CSR must be ready before the first aggregation ----
    cudaStreamWaitEvent(0, ev_join, 0);

    // layer 1 (agg first: S·(h@W1) == (S·h)@W1):
    agg_kernel<128, false, true><<<AGG_GRID, 256>>>(buf0, nullptr, buf1);   // Z1 = S·h0, rounded
    gemm_tc_kernel<128, true, true><<<dim3(2, MT), 256>>>(buf1, w1, b1, buf0, NN, 256, 128);  // h1
    // layer 2 (gemm first):
    gemm_tc_kernel<128, false, false><<<dim3(1, MT), 256>>>(buf0, w2, nullptr, buf1, NN, 128, 256);  // Y2
    agg_kernel<128, true, true><<<AGG_GRID, 256>>>(buf1, b2, buf0);         // h2, rounded
    // layer 3 (gemm first):
    gemm_tc_kernel<64, false, false><<<dim3(1, MT), 256>>>(buf0, w3, nullptr, buf1, NN, 64, 128);    // Y3
    // h3 = lrelu(S·Y3 + b3); out = h3 @ W_out + b_out  (fused)
    agg64_out_kernel<<<AGG_GRID, 256>>>(buf1, b3, Wo, bo, out);
}

// round 7
// speedup vs baseline: 1.7225x; 1.0082x over previous
#include <cuda_runtime.h>
#include <cstdint>

#define NN 50000
#define EE 800000

// ---------------- scratch (static device globals; no allocation) ----------------
__device__ float g_buf0[NN * 256];
__device__ float g_buf1[NN * 256];
__device__ float g_dis[NN];
__device__ int   g_deg[NN];
__device__ int   g_off[NN + 1];
__device__ int   g_cur[NN];
__device__ int2  g_edge[EE];   // {src, float_bits(dis[s]*dis[d])}
// pre-rounded (tf32-representable) weights
__device__ float g_w0[128 * 128];
__device__ float g_w1[128 * 256];
__device__ float g_w2[256 * 128];
__device__ float g_w3[128 * 64];

__device__ __forceinline__ uint32_t f2tf32(float x) {
    uint32_t r;
    asm("cvt.rna.tf32.f32 %0, %1;" : "=r"(r) : "f"(x));
    return r;
}
__device__ __forceinline__ float tf32r(float x) { return __uint_as_float(f2tf32(x)); }

// ---------------- fused weight rounding: 4 weight tensors -> globals ----------------
#define W0F4 (128 * 128 / 4)
#define W1F4 (128 * 256 / 4)
#define W2F4 (256 * 128 / 4)
#define W3F4 (128 * 64 / 4)
#define WTOT (W0F4 + W1F4 + W2F4 + W3F4)

__global__ void round_w_kernel(
    const float* __restrict__ Wi, const float* __restrict__ W1,
    const float* __restrict__ W2, const float* __restrict__ W3) {
    int i = blockIdx.x * blockDim.x + threadIdx.x;
    if (i >= WTOT) return;
    const float4* s;
    float4* d;
    int j;
    if (i < W0F4) { s = (const float4*)Wi; d = (float4*)g_w0; j = i; }
    else if (i < W0F4 + W1F4) { s = (const float4*)W1; d = (float4*)g_w1; j = i - W0F4; }
    else if (i < W0F4 + W1F4 + W2F4) { s = (const float4*)W2; d = (float4*)g_w2; j = i - W0F4 - W1F4; }
    else { s = (const float4*)W3; d = (float4*)g_w3; j = i - W0F4 - W1F4 - W2F4; }
    float4 v = s[j];
    v.x = tf32r(v.x); v.y = tf32r(v.y); v.z = tf32r(v.z); v.w = tf32r(v.w);
    d[j] = v;
}

// ---------------- graph preprocessing (4 edges/thread for ATOMG MLP) ----------------
__global__ void count_deg_kernel(const int* __restrict__ dst) {
    int i = (blockIdx.x * blockDim.x + threadIdx.x) * 4;
    if (i < EE) {  // EE % 4 == 0, loads stay in-bounds
        int4 d = *(const int4*)(dst + i);
        atomicAdd(&g_deg[d.x], 1);
        atomicAdd(&g_deg[d.y], 1);
        atomicAdd(&g_deg[d.z], 1);
        atomicAdd(&g_deg[d.w], 1);
    }
}

// Single-block exclusive scan over deg -> offsets; also dis = rsqrt(deg+1), cursor init.
__global__ void scan_kernel() {
    __shared__ int s[1024];
    const int t = threadIdx.x;
    const int CH = (NN + 1023) / 1024;  // 49
    int start = t * CH;
    int end = min(start + CH, NN);
    int sum = 0;
    for (int i = start; i < end; i++) sum += g_deg[i];
    s[t] = sum;
    __syncthreads();
    for (int off = 1; off < 1024; off <<= 1) {
        int v = (t >= off) ? s[t - off] : 0;
        __syncthreads();
        s[t] += v;
        __syncthreads();
    }
    int run = (t == 0) ? 0 : s[t - 1];
    for (int i = start; i < end; i++) {
        g_off[i] = run;
        g_cur[i] = run;
        g_dis[i] = rsqrtf((float)(g_deg[i] + 1));
        run += g_deg[i];
    }
    if (start < NN && end == NN) g_off[NN] = run;
}

__global__ void fill_csr_kernel(const int* __restrict__ src, const int* __restrict__ dst) {
    int i = (blockIdx.x * blockDim.x + threadIdx.x) * 4;
    if (i < EE) {
        int4 s4 = *(const int4*)(src + i);
        int4 d4 = *(const int4*)(dst + i);
        int p0 = atomicAdd(&g_cur[d4.x], 1);
        int p1 = atomicAdd(&g_cur[d4.y], 1);
        int p2 = atomicAdd(&g_cur[d4.z], 1);
        int p3 = atomicAdd(&g_cur[d4.w], 1);
        g_edge[p0] = make_int2(s4.x, __float_as_int(g_dis[s4.x] * g_dis[d4.x]));
        g_edge[p1] = make_int2(s4.y, __float_as_int(g_dis[s4.y] * g_dis[d4.y]));
        g_edge[p2] = make_int2(s4.z, __float_as_int(g_dis[s4.z] * g_dis[d4.z]));
        g_edge[p3] = make_int2(s4.w, __float_as_int(g_dis[s4.w] * g_dis[d4.w]));
    }
}

// ---------------- TF32 tensor-core GEMM with cp.async pipeline ----------------
// Inputs must be tf32-representable, EXCEPT when CVT_A: A is rounded in the load path.
// Block tile: 128 x NT. 8 warps (4 m x 2 n). K-chunk 32, 2-stage double buffering.

#define MMA_TF32(d, a, b)                                                             \
    asm volatile(                                                                     \
        "mma.sync.aligned.m16n8k8.row.col.f32.tf32.tf32.f32 "                         \
        "{%0,%1,%2,%3}, {%4,%5,%6,%7}, {%8,%9}, {%0,%1,%2,%3};"                       \
        : "+f"((d)[0]), "+f"((d)[1]), "+f"((d)[2]), "+f"((d)[3])                      \
        : "r"((a)[0]), "r"((a)[1]), "r"((a)[2]), "r"((a)[3]), "r"((b)[0]), "r"((b)[1]))

__device__ __forceinline__ void cp_async16(uint32_t smem_addr, const void* gptr) {
    asm volatile("cp.async.cg.shared.global [%0], [%1], 16;\n" ::"r"(smem_addr), "l"(gptr));
}
__device__ __forceinline__ void cp_commit() { asm volatile("cp.async.commit_group;\n"); }
template <int W>
__device__ __forceinline__ void cp_wait() { asm volatile("cp.async.wait_group %0;\n" ::"n"(W)); }

template <int NT, bool BIAS_ACT, bool ROUND, bool CVT_A>
__global__ __launch_bounds__(256) void gemm_tc_kernel(
    const float* __restrict__ A, const float* __restrict__ B,
    const float* __restrict__ bias, float* __restrict__ C,
    int M, int N, int K) {
    constexpr int NF = NT / 16;
    constexpr int BS = NT + 4;
    constexpr int NB = NT / 32;
    __shared__ uint32_t As[2][128 * 36];
    __shared__ uint32_t Bs[2][32 * BS];

    const int tid = threadIdx.x;
    const int lane = tid & 31;
    const int wid = tid >> 5;
    const int wm = (wid & 3) * 32;
    const int wn = (wid >> 2) * (NT / 2);
    const int g = lane >> 2;
    const int t4 = lane & 3;
    const int bm = blockIdx.y * 128;
    const int bn = blockIdx.x * NT;

    const int aR = tid >> 3;
    const int aC = (tid & 7) * 4;
    const int bR = tid / (NT / 4);
    const int bC = (tid % (NT / 4)) * 4;

    auto issue_A = [&](int k0, int st) {  // cp.async path (pre-rounded A)
#pragma unroll
        for (int it = 0; it < 4; it++) {
            int r = it * 32 + aR;
            int gr = min(bm + r, M - 1);
            uint32_t da = (uint32_t)__cvta_generic_to_shared(&As[st][r * 36 + aC]);
            cp_async16(da, A + (size_t)gr * K + k0 + aC);
        }
    };
    auto issue_B = [&](int k0, int st) {
        constexpr int RPI = 256 / (NT / 4);
#pragma unroll
        for (int it = 0; it < NB; it++) {
            int r = it * RPI + bR;
            uint32_t db = (uint32_t)__cvta_generic_to_shared(&Bs[st][r * BS + bC]);
            cp_async16(db, B + (size_t)(k0 + r) * N + bn + bC);
        }
    };

    float4 ar[4];  // CVT_A register staging
    auto load_A_regs = [&](int k0) {
#pragma unroll
        for (int it = 0; it < 4; it++) {
            int r = it * 32 + aR;
            int gr = min(bm + r, M - 1);
            ar[it] = *(const float4*)(A + (size_t)gr * K + k0 + aC);
        }
    };
    auto sts_A_regs = [&](int st) {
#pragma unroll
        for (int it = 0; it < 4; it++) {
            int r = it * 32 + aR;
            uint32_t* p = &As[st][r * 36 + aC];
            p[0] = f2tf32(ar[it].x); p[1] = f2tf32(ar[it].y);
            p[2] = f2tf32(ar[it].z); p[3] = f2tf32(ar[it].w);
        }
    };

    float c[2][NF][4] = {};
    const int nch = K >> 5;

    if (CVT_A) load_A_regs(0); else issue_A(0, 0);
    issue_B(0, 0);
    cp_commit();

    for (int i = 0; i < nch; i++) {
        const int st = i & 1;
        if (CVT_A) sts_A_regs(st);
        if (i + 1 < nch) {
            if (!CVT_A) issue_A((i + 1) << 5, st ^ 1);
            issue_B((i + 1) << 5, st ^ 1);
            cp_commit();
            if (CVT_A) load_A_regs((i + 1) << 5);  // LDG overlapped with MMA below
            cp_wait<1>();
        } else {
            cp_wait<0>();
        }
        __syncthreads();

#pragma unroll
        for (int s = 0; s < 4; s++) {
            uint32_t a[2][4];
#pragma unroll
            for (int mf = 0; mf < 2; mf++) {
                int r0 = (wm + mf * 16 + g) * 36 + s * 8 + t4;
                int r1 = (wm + mf * 16 + g + 8) * 36 + s * 8 + t4;
                a[mf][0] = As[st][r0];
                a[mf][1] = As[st][r1];
                a[mf][2] = As[st][r0 + 4];
                a[mf][3] = As[st][r1 + 4];
            }
            uint32_t b[NF][2];
#pragma unroll
            for (int nf = 0; nf < NF; nf++) {
                int col = wn + nf * 8 + g;
                b[nf][0] = Bs[st][(s * 8 + t4) * BS + col];
                b[nf][1] = Bs[st][(s * 8 + t4 + 4) * BS + col];
            }
#pragma unroll
            for (int mf = 0; mf < 2; mf++)
#pragma unroll
                for (int nf = 0; nf < NF; nf++) MMA_TF32(c[mf][nf], a[mf], b[nf]);
        }
        __syncthreads();
    }

#pragma unroll
    for (int mf = 0; mf < 2; mf++) {
        int r0 = bm + wm + mf * 16 + g;
        int r1 = r0 + 8;
#pragma unroll
        for (int nf = 0; nf < NF; nf++) {
            int col = bn + wn + nf * 8 + 2 * t4;
            float v0 = c[mf][nf][0], v1 = c[mf][nf][1];
            float v2 = c[mf][nf][2], v3 = c[mf][nf][3];
            if (BIAS_ACT) {
                float bb0 = bias[col], bb1 = bias[col + 1];
                v0 += bb0; v1 += bb1; v2 += bb0; v3 += bb1;
                v0 = v0 > 0.f ? v0 : 0.01f * v0;
                v1 = v1 > 0.f ? v1 : 0.01f * v1;
                v2 = v2 > 0.f ? v2 : 0.01f * v2;
                v3 = v3 > 0.f ? v3 : 0.01f * v3;
            }
            if (ROUND) {
                v0 = tf32r(v0); v1 = tf32r(v1); v2 = tf32r(v2); v3 = tf32r(v3);
            }
            if (r0 < M) { float2 o; o.x = v0; o.y = v1; *(float2*)(C + (size_t)r0 * N + col) = o; }
            if (r1 < M) { float2 o; o.x = v2; o.y = v3; *(float2*)(C + (size_t)r1 * N + col) = o; }
        }
    }
}

// ---------------- gather aggregation: H = [lrelu](S·Y [+ b]) ----------------
// One warp per node, packed edges, 8-deep gather batching for MLP.
template <int C, bool BIAS_ACT, bool ROUND>
__global__ __launch_bounds__(256) void agg_kernel(
    const float* __restrict__ Y, const float* __restrict__ bias, float* __restrict__ H) {
    int node = (blockIdx.x * blockDim.x + threadIdx.x) >> 5;
    int lane = threadIdx.x & 31;
    if (node >= NN) return;

    float dn = g_dis[node];
    float selfw = dn * dn;
    int beg = g_off[node];
    int end = g_off[node + 1];

    float4 acc;
    {
        float4 u = ((const float4*)(Y + (size_t)node * C))[lane];
        acc.x = selfw * u.x; acc.y = selfw * u.y;
        acc.z = selfw * u.z; acc.w = selfw * u.w;
    }
    int i = beg;
    for (; i + 8 <= end; i += 8) {
        int2 e[8];
#pragma unroll
        for (int j = 0; j < 8; j++) e[j] = g_edge[i + j];
        float4 u[8];
#pragma unroll
        for (int j = 0; j < 8; j++) u[j] = ((const float4*)(Y + (size_t)e[j].x * C))[lane];
#pragma unroll
        for (int j = 0; j < 8; j++) {
            float w = __int_as_float(e[j].y);
            acc.x += w * u[j].x;
            acc.y += w * u[j].y;
            acc.z += w * u[j].z;
            acc.w += w * u[j].w;
        }
    }
    for (; i < end; i++) {
        int2 e = g_edge[i];
        float w = __int_as_float(e.y);
        float4 u = ((const float4*)(Y + (size_t)e.x * C))[lane];
        acc.x += w * u.x;
        acc.y += w * u.y;
        acc.z += w * u.z;
        acc.w += w * u.w;
    }
    if (BIAS_ACT) {
        float4 b = ((const float4*)bias)[lane];
        acc.x += b.x; acc.y += b.y; acc.z += b.z; acc.w += b.w;
        acc.x = acc.x > 0.f ? acc.x : 0.01f * acc.x;
        acc.y = acc.y > 0.f ? acc.y : 0.01f * acc.y;
        acc.z = acc.z > 0.f ? acc.z : 0.01f * acc.z;
        acc.w = acc.w > 0.f ? acc.w : 0.01f * acc.w;
    }
    if (ROUND) {
        acc.x = tf32r(acc.x); acc.y = tf32r(acc.y);
        acc.z = tf32r(acc.z); acc.w = tf32r(acc.w);
    }
    ((float4*)(H + (size_t)node * C))[lane] = acc;
}

// ---------------- final agg (C=64) fused with output projection ----------------
__global__ __launch_bounds__(256) void agg64_out_kernel(
    const float* __restrict__ Y, const float* __restrict__ bias,
    const float* __restrict__ Wout, const float* __restrict__ bout,
    float* __restrict__ out) {
    int node = (blockIdx.x * blockDim.x + threadIdx.x) >> 5;
    int lane = threadIdx.x & 31;
    if (node >= NN) return;

    float dn = g_dis[node];
    float selfw = dn * dn;
    int beg = g_off[node];
    int end = g_off[node + 1];

    float2 acc;
    {
        float2 u = ((const float2*)(Y + (size_t)node * 64))[lane];
        acc.x = selfw * u.x;
        acc.y = selfw * u.y;
    }
    int i = beg;
    for (; i + 8 <= end; i += 8) {
        int2 e[8];
#pragma unroll
        for (int j = 0; j < 8; j++) e[j] = g_edge[i + j];
        float2 u[8];
#pragma unroll
        for (int j = 0; j < 8; j++) u[j] = ((const float2*)(Y + (size_t)e[j].x * 64))[lane];
#pragma unroll
        for (int j = 0; j < 8; j++) {
            float w = __int_as_float(e[j].y);
            acc.x += w * u[j].x;
            acc.y += w * u[j].y;
        }
    }
    for (; i < end; i++) {
        int2 e = g_edge[i];
        float w = __int_as_float(e.y);
        float2 u = ((const float2*)(Y + (size_t)e.x * 64))[lane];
        acc.x += w * u.x;
        acc.y += w * u.y;
    }
    float2 b = ((const float2*)bias)[lane];
    acc.x += b.x; acc.y += b.y;
    acc.x = acc.x > 0.f ? acc.x : 0.01f * acc.x;
    acc.y = acc.y > 0.f ? acc.y : 0.01f * acc.y;

    float2 w = ((const float2*)Wout)[lane];
    float v = acc.x * w.x + acc.y * w.y;
#pragma unroll
    for (int o = 16; o > 0; o >>= 1) v += __shfl_down_sync(0xffffffffu, v, o);
    if (lane == 0) out[node] = v + bout[0];
}

// ---------------- launch ----------------
extern "C" void kernel_launch(void* const* d_in, const int* in_sizes, int n_in,
                              void* d_out, int out_size) {
    const float* x    = (const float*)d_in[0];
    const int*   ei   = (const int*)d_in[1];
    const float* W_in = (const float*)d_in[2];
    const float* b_in = (const float*)d_in[3];
    const float* W1   = (const float*)d_in[4];
    const float* b1   = (const float*)d_in[5];
    const float* W2   = (const float*)d_in[6];
    const float* b2   = (const float*)d_in[7];
    const float* W3   = (const float*)d_in[8];
    const float* b3   = (const float*)d_in[9];
    const float* Wo   = (const float*)d_in[10];
    const float* bo   = (const float*)d_in[11];
    float* out = (float*)d_out;

    const int* src = ei;
    const int* dst = ei + EE;

    float *buf0, *buf1, *w0, *w1, *w2, *w3;
    cudaGetSymbolAddress((void**)&buf0, g_buf0);
    cudaGetSymbolAddress((void**)&buf1, g_buf1);
    cudaGetSymbolAddress((void**)&w0, g_w0);
    cudaGetSymbolAddress((void**)&w1, g_w1);
    cudaGetSymbolAddress((void**)&w2, g_w2);
    cudaGetSymbolAddress((void**)&w3, g_w3);
    int* degp;
    cudaGetSymbolAddress((void**)&degp, g_deg);

    // lazily created side-stream + events (host resources only; no device memory)
    static cudaStream_t s2 = nullptr;
    static cudaEvent_t ev_fork = nullptr, ev_join = nullptr;
    if (s2 == nullptr) {
        cudaStreamCreateWithFlags(&s2, cudaStreamNonBlocking);
        cudaEventCreateWithFlags(&ev_fork, cudaEventDisableTiming);
        cudaEventCreateWithFlags(&ev_join, cudaEventDisableTiming);
    }

    // ---- fork: preprocessing on s2, concurrent with round_w+gemm0 on main stream ----
    cudaEventRecord(ev_fork, 0);
    cudaStreamWaitEvent(s2, ev_fork, 0);

    cudaMemsetAsync(degp, 0, NN * sizeof(int), s2);
    count_deg_kernel<<<(EE / 4 + 255) / 256, 256, 0, s2>>>(dst);
    scan_kernel<<<1, 1024, 0, s2>>>();
    fill_csr_kernel<<<(EE / 4 + 255) / 256, 256, 0, s2>>>(src, dst);
    cudaEventRecord(ev_join, s2);

    // main stream: round weights, then gemm0 (x rounded in its A-load path)
    round_w_kernel<<<(WTOT + 255) / 256, 256>>>(W_in, W1, W2, W3);

    const int MT = (NN + 127) / 128;
    const int AGG_GRID = (NN + 7) / 8;

    // h0 = lrelu(x @ W_in + b_in), rounded                 [N,128]
    gemm_tc_kernel<128, true, true, true><<<dim3(1, MT), 256>>>(x, w0, b_in, buf0, NN, 128, 128);

    // ---- join: CSR must be ready before the first aggregation ----
    cudaStreamWaitEvent(0, ev_join, 0);

    // layer 1 (agg first: S·(h@W1) == (S·h)@W1):
    agg_kernel<128, false, true><<<AGG_GRID, 256>>>(buf0, nullptr, buf1);   // Z1 = S·h0, rounded
    gemm_tc_kernel<128, true, true, false><<<dim3(2, MT), 256>>>(buf1, w1, b1, buf0, NN, 256, 128);  // h1
    // layer 2 (gemm first):
    gemm_tc_kernel<128, false, false, false><<<dim3(1, MT), 256>>>(buf0, w2, nullptr, buf1, NN, 128, 256);  // Y2
    agg_kernel<128, true, true><<<AGG_GRID, 256>>>(buf1, b2, buf0);         // h2, rounded
    // layer 3 (gemm first):
    gemm_tc_kernel<64, false, false, false><<<dim3(1, MT), 256>>>(buf0, w3, nullptr, buf1, NN, 64, 128);    // Y3
    // h3 = lrelu(S·Y3 + b3); out = h3 @ W_out + b_out  (fused)
    agg64_out_kernel<<<AGG_GRID, 256>>>(buf1, b3, Wo, bo, out);
}